// round 2
// baseline (speedup 1.0000x reference)
#include <cuda_runtime.h>
#include <math.h>

#define B_  4
#define S_  2048
#define D_  1024
#define H_  4
#define HD_ 256
#define LN_EPS 1e-5f

// ---------------- device scratch (no cudaMalloc allowed) ----------------
__device__ float g_Q[(size_t)B_*H_*S_*HD_];          // [b,h,s,e]
__device__ float g_Kb[(size_t)B_*H_*S_*HD_];         // [b,h,s,e]
__device__ float g_Vt[(size_t)B_*H_*HD_*S_];         // [b,h,e,t]  (V transposed)
__device__ float g_W[(size_t)B_*H_*S_*S_];           // scores -> weights, 268MB
__device__ float g_concat[(size_t)B_*S_*D_];         // [b,s,d]
__device__ float g_wo[(size_t)B_*S_*D_];             // Wo output pre-LN
__device__ float g_mag1[B_*S_];
__device__ float g_v3[B_*S_];
__device__ float g_mean;

// ---------------- block reductions ----------------
__device__ __forceinline__ float blockReduceSum(float v) {
    __shared__ float sh[33];
    __syncthreads();
    #pragma unroll
    for (int o = 16; o; o >>= 1) v += __shfl_xor_sync(0xffffffffu, v, o);
    if ((threadIdx.x & 31) == 0) sh[threadIdx.x >> 5] = v;
    __syncthreads();
    if (threadIdx.x < 32) {
        v = (threadIdx.x < (blockDim.x >> 5)) ? sh[threadIdx.x] : 0.f;
        #pragma unroll
        for (int o = 16; o; o >>= 1) v += __shfl_xor_sync(0xffffffffu, v, o);
        if (threadIdx.x == 0) sh[32] = v;
    }
    __syncthreads();
    return sh[32];
}

__device__ __forceinline__ float blockReduceMax(float v) {
    __shared__ float sh[33];
    __syncthreads();
    #pragma unroll
    for (int o = 16; o; o >>= 1) v = fmaxf(v, __shfl_xor_sync(0xffffffffu, v, o));
    if ((threadIdx.x & 31) == 0) sh[threadIdx.x >> 5] = v;
    __syncthreads();
    if (threadIdx.x < 32) {
        v = (threadIdx.x < (blockDim.x >> 5)) ? sh[threadIdx.x] : -INFINITY;
        #pragma unroll
        for (int o = 16; o; o >>= 1) v = fmaxf(v, __shfl_xor_sync(0xffffffffu, v, o));
        if (threadIdx.x == 0) sh[32] = v;
    }
    __syncthreads();
    return sh[32];
}

// ---------------- generic batched NT SGEMM: C = alpha * A @ B^T ----------------
// A: [M,K] rows K-major, row stride lda. B: [N,K] rows K-major, row stride ldb.
// C element (m,n) at C + m*Crs + n*Ccs. Batch z -> (b = z/Hdiv, h = z%Hdiv).
// Requires M,N multiples of 128, K multiple of 8, 16B-aligned bases & lda/ldb mult of 4.
__global__ __launch_bounds__(256)
void sgemm_nt(const float* __restrict__ A, const float* __restrict__ Bm,
              float* __restrict__ C, int K, int lda, int ldb,
              long long Asb, long long Ash, long long Bsb, long long Bsh,
              long long Csb, long long Csh, long long Crs, long long Ccs,
              float alpha, int Hdiv)
{
    int z = blockIdx.z;
    int b = z / Hdiv, h = z % Hdiv;
    A  += b * Asb + h * Ash;
    Bm += b * Bsb + h * Bsh;
    C  += b * Csb + h * Csh;

    __shared__ __align__(16) float As[8][128];
    __shared__ __align__(16) float Bs[8][128];

    int tid = threadIdx.x;
    int lr = tid >> 1;           // 0..127
    int lk = (tid & 1) * 4;      // 0 or 4
    int m0 = blockIdx.y * 128, n0 = blockIdx.x * 128;

    const float* Ap = A  + (long long)(m0 + lr) * lda + lk;
    const float* Bp = Bm + (long long)(n0 + lr) * ldb + lk;

    int tx = tid & 15, ty = tid >> 4;

    float acc[8][8];
    #pragma unroll
    for (int i = 0; i < 8; i++)
        #pragma unroll
        for (int j = 0; j < 8; j++) acc[i][j] = 0.f;

    for (int k0 = 0; k0 < K; k0 += 8) {
        float4 av = *(const float4*)(Ap + k0);
        float4 bv = *(const float4*)(Bp + k0);
        __syncthreads();
        As[lk + 0][lr] = av.x; As[lk + 1][lr] = av.y;
        As[lk + 2][lr] = av.z; As[lk + 3][lr] = av.w;
        Bs[lk + 0][lr] = bv.x; Bs[lk + 1][lr] = bv.y;
        Bs[lk + 2][lr] = bv.z; Bs[lk + 3][lr] = bv.w;
        __syncthreads();
        #pragma unroll
        for (int kk = 0; kk < 8; kk++) {
            float a[8], bb[8];
            *(float4*)(a)      = *(const float4*)&As[kk][ty * 4];
            *(float4*)(a + 4)  = *(const float4*)&As[kk][64 + ty * 4];
            *(float4*)(bb)     = *(const float4*)&Bs[kk][tx * 4];
            *(float4*)(bb + 4) = *(const float4*)&Bs[kk][64 + tx * 4];
            #pragma unroll
            for (int i = 0; i < 8; i++)
                #pragma unroll
                for (int j = 0; j < 8; j++)
                    acc[i][j] += a[i] * bb[j];
        }
    }

    #pragma unroll
    for (int i = 0; i < 8; i++) {
        int m = m0 + ((i < 4) ? (ty * 4 + i) : (64 + ty * 4 + i - 4));
        #pragma unroll
        for (int j = 0; j < 8; j++) {
            int n = n0 + ((j < 4) ? (tx * 4 + j) : (64 + tx * 4 + j - 4));
            C[(long long)m * Crs + (long long)n * Ccs] = alpha * acc[i][j];
        }
    }
}

// ---------------- mag1 / v3 ----------------
__global__ __launch_bounds__(256) void mag_kernel(const float* __restrict__ emb) {
    int row = blockIdx.x;             // b*S + s
    int tid = threadIdx.x;            // 256 = hd
    float v = emb[(long long)row * D_ + HD_ + tid];   // head 1 slice
    float ss = blockReduceSum(v * v);
    if (tid == 0) {
        g_mag1[row] = sqrtf(ss);
        g_v3[row]   = emb[(long long)row * D_ + (D_ - 1)];  // head 3, last feature
    }
}

// deterministic intent.mean() = sum_b (sum_s mag1[b,s])^2 / (B*S*S)
__global__ __launch_bounds__(256) void mean_kernel() {
    int tid = threadIdx.x;
    float acc = 0.f;
    for (int b = 0; b < B_; b++) {
        float v = 0.f;
        for (int i = tid; i < S_; i += 256) v += g_mag1[b * S_ + i];
        v = blockReduceSum(v);
        acc += v * v;
    }
    if (tid == 0) g_mean = acc / ((float)B_ * (float)S_ * (float)S_);
}

// ---------------- bias + softmax (in-place on g_W) ----------------
__global__ __launch_bounds__(256) void softmax_kernel(const float* __restrict__ bias_scalars) {
    int s = blockIdx.x, h = blockIdx.y, b = blockIdx.z;
    int tid = threadIdx.x;
    float* row = g_W + (((long long)(b * H_ + h)) * S_ + s) * S_;
    float bs = bias_scalars[h];
    float mean = g_mean;
    float ms = g_mag1[b * S_ + s];
    float vs = g_v3[b * S_ + s];

    float vals[8];
    #pragma unroll
    for (int i = 0; i < 8; i++) {
        int t = tid + i * 256;
        float x = row[t];
        float bias;
        if (h == 0)      bias = (t > s) ? bs : 0.f;
        else if (h == 1) bias = (ms * g_mag1[b * S_ + t] > mean) ? bs : 0.f;
        else if (h == 2) bias = expf(fabsf((float)(t - s)) * (-1.f / (float)S_)) * bs;
        else             bias = (vs * g_v3[b * S_ + t] > 0.5f) ? bs : 0.f;
        vals[i] = x + bias;
    }
    float m = -INFINITY;
    #pragma unroll
    for (int i = 0; i < 8; i++) m = fmaxf(m, vals[i]);
    m = blockReduceMax(m);
    float sum = 0.f;
    #pragma unroll
    for (int i = 0; i < 8; i++) { vals[i] = expf(vals[i] - m); sum += vals[i]; }
    sum = blockReduceSum(sum);
    float inv = 1.f / sum;
    #pragma unroll
    for (int i = 0; i < 8; i++) row[tid + i * 256] = vals[i] * inv;
}

// ---------------- head-average of weights -> output region 1 ----------------
__global__ __launch_bounds__(256) void avg_kernel(float* __restrict__ outAvg) {
    long long idx = (long long)blockIdx.x * 256 + threadIdx.x;  // float4 units
    const long long bq = (long long)S_ * S_ / 4;                // per (b,h) chunk
    int b = (int)(idx / bq);
    long long r = idx - (long long)b * bq;
    const float4* w4 = (const float4*)g_W;
    float4 a0 = w4[((long long)(b * H_ + 0)) * bq + r];
    float4 a1 = w4[((long long)(b * H_ + 1)) * bq + r];
    float4 a2 = w4[((long long)(b * H_ + 2)) * bq + r];
    float4 a3 = w4[((long long)(b * H_ + 3)) * bq + r];
    float4 o;
    o.x = 0.25f * (a0.x + a1.x + a2.x + a3.x);
    o.y = 0.25f * (a0.y + a1.y + a2.y + a3.y);
    o.z = 0.25f * (a0.z + a1.z + a2.z + a3.z);
    o.w = 0.25f * (a0.w + a1.w + a2.w + a3.w);
    ((float4*)outAvg)[idx] = o;
}

// guilt = softmax over rows that all sum to exactly 1 -> uniform 1/S
__global__ void guilt_kernel(float* __restrict__ outG) {
    int i = blockIdx.x * 256 + threadIdx.x;
    if (i < B_ * S_) outG[i] = 1.0f / (float)S_;
}

// ---------------- bias + residual + LayerNorm ----------------
__global__ __launch_bounds__(256) void ln_kernel(const float* __restrict__ emb,
                                                 const float* __restrict__ Wo_b,
                                                 const float* __restrict__ gam,
                                                 const float* __restrict__ bet,
                                                 float* __restrict__ outp) {
    int tok = blockIdx.x;
    int tid = threadIdx.x;
    float y[4];
    float s1 = 0.f;
    #pragma unroll
    for (int i = 0; i < 4; i++) {
        int d = tid + i * 256;
        y[i] = g_wo[(long long)tok * D_ + d] + Wo_b[d] + emb[(long long)tok * D_ + d];
        s1 += y[i];
    }
    s1 = blockReduceSum(s1);
    float mu = s1 * (1.f / (float)D_);
    float s2 = 0.f;
    #pragma unroll
    for (int i = 0; i < 4; i++) { float dd = y[i] - mu; s2 += dd * dd; }
    s2 = blockReduceSum(s2);
    float inv = rsqrtf(s2 * (1.f / (float)D_) + LN_EPS);
    #pragma unroll
    for (int i = 0; i < 4; i++) {
        int d = tid + i * 256;
        outp[(long long)tok * D_ + d] = (y[i] - mu) * inv * gam[d] + bet[d];
    }
}

// ---------------- launch ----------------
extern "C" void kernel_launch(void* const* d_in, const int* in_sizes, int n_in,
                              void* d_out, int out_size) {
    const float* emb   = (const float*)d_in[0];
    const float* Wq    = (const float*)d_in[1];
    const float* Wk    = (const float*)d_in[2];
    const float* Wv    = (const float*)d_in[3];
    const float* bsc   = (const float*)d_in[4];
    const float* Wo_w  = (const float*)d_in[5];
    const float* Wo_b  = (const float*)d_in[6];
    const float* ln_g  = (const float*)d_in[7];
    const float* ln_b  = (const float*)d_in[8];
    float* out = (float*)d_out;

    float *pQ, *pK, *pVt, *pW, *pC, *pO;
    cudaGetSymbolAddress((void**)&pQ, g_Q);
    cudaGetSymbolAddress((void**)&pK, g_Kb);
    cudaGetSymbolAddress((void**)&pVt, g_Vt);
    cudaGetSymbolAddress((void**)&pW, g_W);
    cudaGetSymbolAddress((void**)&pC, g_concat);
    cudaGetSymbolAddress((void**)&pO, g_wo);

    const long long SD  = (long long)S_ * D_;
    const long long SH  = (long long)S_ * HD_;
    const long long SS  = (long long)S_ * S_;

    dim3 blk(256);

    // Q = X @ Wq^T   (per b,h: A = emb head slice, lda = D)
    sgemm_nt<<<dim3(2, 16, 16), blk>>>(emb, Wq, pQ, HD_, D_, HD_,
        SD, HD_, 0, (long long)HD_ * HD_,
        (long long)H_ * SH, SH, HD_, 1, 1.0f, H_);
    // K
    sgemm_nt<<<dim3(2, 16, 16), blk>>>(emb, Wk, pK, HD_, D_, HD_,
        SD, HD_, 0, (long long)HD_ * HD_,
        (long long)H_ * SH, SH, HD_, 1, 1.0f, H_);
    // V, stored transposed: Vt[b,h,e,t]
    sgemm_nt<<<dim3(2, 16, 16), blk>>>(emb, Wv, pVt, HD_, D_, HD_,
        SD, HD_, 0, (long long)HD_ * HD_,
        (long long)H_ * SH, SH, 1, S_, 1.0f, H_);

    // mag1 / v3 / intent mean
    mag_kernel<<<B_ * S_, 256>>>(emb);
    mean_kernel<<<1, 256>>>();

    // scores = (Q @ K^T) / sqrt(hd)
    sgemm_nt<<<dim3(16, 16, 16), blk>>>(pQ, pK, pW, HD_, HD_, HD_,
        (long long)H_ * SH, SH, (long long)H_ * SH, SH,
        (long long)H_ * SS, SS, S_, 1, 0.0625f, H_);

    // + biases, softmax (in place)
    softmax_kernel<<<dim3(S_, H_, B_), 256>>>(bsc);

    // average weights + guilt -> output regions 1 & 2
    avg_kernel<<<(B_ * S_ * S_) / 4 / 256, 256>>>(out + (long long)B_ * SD);
    guilt_kernel<<<(B_ * S_ + 255) / 256, 256>>>(out + (long long)B_ * SD + (long long)B_ * SS);

    // attended = W @ V  -> concat layout [b,s,h*hd+e]
    sgemm_nt<<<dim3(2, 16, 16), blk>>>(pW, pVt, pC, S_, S_, S_,
        (long long)H_ * SS, SS, (long long)H_ * HD_ * S_, (long long)HD_ * S_,
        SD, HD_, D_, 1, 1.0f, H_);

    // out = concat @ Wo^T   (single batch, M = B*S)
    sgemm_nt<<<dim3(8, 64, 1), blk>>>(pC, Wo_w, pO, D_, D_, D_,
        0, 0, 0, 0, 0, 0, D_, 1, 1.0f, 1);

    // + Wo_b + residual + LayerNorm -> output region 0
    ln_kernel<<<B_ * S_, 256>>>(emb, Wo_b, ln_g, ln_b, out);
}

// round 5
// speedup vs baseline: 1.9258x; 1.9258x over previous
#include <cuda_runtime.h>
#include <cuda_bf16.h>
#include <math.h>

#define B_  4
#define S_  2048
#define D_  1024
#define H_  4
#define HD_ 256
#define LN_EPS 1e-5f

typedef unsigned int       u32;
typedef unsigned long long u64;

// ---------------- device scratch (no cudaMalloc allowed) ----------------
// split bf16 arrays: hi plane at [0, N), lo plane at [N, 2N)
__device__ __align__(16) float          g_S [(size_t)B_*H_*S_*S_];     // fp32 scores
__device__ __align__(16) __nv_bfloat16  g_Ws[2*(size_t)B_*H_*S_*S_];   // softmax weights split
__device__ __align__(16) __nv_bfloat16  g_Qs[2*(size_t)B_*H_*S_*HD_];
__device__ __align__(16) __nv_bfloat16  g_Ks[2*(size_t)B_*H_*S_*HD_];
__device__ __align__(16) __nv_bfloat16  g_Vts[2*(size_t)B_*H_*HD_*S_]; // V transposed [b,h,e,t]
__device__ __align__(16) __nv_bfloat16  g_embs[2*(size_t)B_*S_*D_];
__device__ __align__(16) __nv_bfloat16  g_Wqs[2*(size_t)H_*HD_*HD_];
__device__ __align__(16) __nv_bfloat16  g_Wks[2*(size_t)H_*HD_*HD_];
__device__ __align__(16) __nv_bfloat16  g_Wvs[2*(size_t)H_*HD_*HD_];
__device__ __align__(16) __nv_bfloat16  g_Wos[2*(size_t)D_*D_];
__device__ __align__(16) __nv_bfloat16  g_Cs[2*(size_t)B_*S_*D_];      // concat split
__device__ __align__(16) float          g_wo[(size_t)B_*S_*D_];        // Wo output pre-LN
__device__ float g_mag1[B_*S_];
__device__ float g_v3[B_*S_];
__device__ float g_mean;

// ---------------- helpers ----------------
__device__ __forceinline__ u32 smem_to_u32(const void* p) {
    u32 a;
    asm("{ .reg .u64 t; cvta.to.shared.u64 t, %1; cvt.u32.u64 %0, t; }" : "=r"(a) : "l"(p));
    return a;
}
static __device__ __forceinline__ u32 swz(u32 o) { return o ^ ((o >> 3) & 0x70u); }

__device__ __forceinline__ void cp_async16(u32 dst, const void* src) {
    asm volatile("cp.async.cg.shared.global [%0], [%1], 16;" :: "r"(dst), "l"(src));
}
#define CP_COMMIT()  asm volatile("cp.async.commit_group;" ::: "memory")
#define CP_WAIT(N)   asm volatile("cp.async.wait_group %0;" :: "n"(N) : "memory")

__device__ __forceinline__ void ldsm4(u32 addr, u32& r0, u32& r1, u32& r2, u32& r3) {
    asm volatile("ldmatrix.sync.aligned.m8n8.x4.shared.b16 {%0,%1,%2,%3}, [%4];"
        : "=r"(r0), "=r"(r1), "=r"(r2), "=r"(r3) : "r"(addr));
}
__device__ __forceinline__ void mma16816(float* c, const u32* a, u32 b0, u32 b1) {
    asm volatile("mma.sync.aligned.m16n8k16.row.col.f32.bf16.bf16.f32 "
        "{%0,%1,%2,%3}, {%4,%5,%6,%7}, {%8,%9}, {%0,%1,%2,%3};"
        : "+f"(c[0]), "+f"(c[1]), "+f"(c[2]), "+f"(c[3])
        : "r"(a[0]), "r"(a[1]), "r"(a[2]), "r"(a[3]), "r"(b0), "r"(b1));
}

// ============================================================================
// Generic batched NT GEMM via mma.sync: C = alpha * (A @ B^T), split-bf16.
// A: hi plane at A, lo at A+Aplane; [M,K] rows K-major, row stride lda.
// CTA tile 128x128, K-chunk 64. 2-stage cp.async pipeline (2 x 64KB smem).
// Stage layout: Ahi @0, Alo @16K, Bhi @32K, Blo @48K (each 128 rows x 128B, SW128).
// Output: outSplit ? split bf16 (Ch/Ch+Cplane) : fp32 Cf; elem (m,n) at m*Crs+n*Ccs.
// ============================================================================
__device__ __forceinline__ void stage_load(u32 sbase, int buf,
    const __nv_bfloat16* A, long long Aplane, int lda, int m0,
    const __nv_bfloat16* Bm, long long Bplane, int ldb, int n0,
    long long kof, int tid)
{
    #pragma unroll
    for (int it = 0; it < 16; it++) {
        int idx = tid + it * 256;
        int tile = idx >> 10;                // 0 Ahi, 1 Alo, 2 Bhi, 3 Blo
        int rem = idx & 1023;
        int r = rem >> 3, c = rem & 7;
        const __nv_bfloat16* src;
        if (tile < 2)
            src = A + (long long)tile * Aplane + (long long)(m0 + r) * lda + kof + c * 8;
        else
            src = Bm + (long long)(tile - 2) * Bplane + (long long)(n0 + r) * ldb + kof + c * 8;
        u32 dst = sbase + (u32)buf * 65536u + (u32)tile * 16384u + swz((u32)(r * 128 + c * 16));
        cp_async16(dst, src);
    }
    CP_COMMIT();
}

__global__ void __launch_bounds__(256, 1)
mma_gemm(const __nv_bfloat16* __restrict__ A, long long Aplane, int lda,
         long long Asb, long long Ash,
         const __nv_bfloat16* __restrict__ Bm, long long Bplane, int ldb,
         long long Bsb, long long Bsh,
         float* __restrict__ Cf, __nv_bfloat16* __restrict__ Ch, long long Cplane,
         long long Csb, long long Csh, long long Crs, long long Ccs,
         int K, float alpha, int Hdiv, int outSplit)
{
    extern __shared__ __align__(16) char smem[];
    const u32 sbase = smem_to_u32(smem);

    int tid = threadIdx.x, lane = tid & 31, wid = tid >> 5;
    int wm = wid & 3, wn = wid >> 2;                 // warp tile 32x64 at (wm*32, wn*64)
    int z = blockIdx.z, b = z / Hdiv, h = z % Hdiv;
    A  += b * Asb + h * Ash;
    Bm += b * Bsb + h * Bsh;
    const long long Cb = b * Csb + h * Csh;

    const int m0 = blockIdx.y * 128, n0 = blockIdx.x * 128;

    // ldmatrix per-lane addressing (row within 16, byte half of k16-step)
    const int ph_row  = (lane & 7) + ((lane >> 3) & 1) * 8;
    const int ph_byte = (lane >> 4) * 16;

    float acc[2][8][4];
    #pragma unroll
    for (int i = 0; i < 2; i++)
        #pragma unroll
        for (int j = 0; j < 8; j++)
            #pragma unroll
            for (int k = 0; k < 4; k++) acc[i][j][k] = 0.f;

    const int nc = K >> 6;
    stage_load(sbase, 0, A, Aplane, lda, m0, Bm, Bplane, ldb, n0, 0,  tid);
    stage_load(sbase, 1, A, Aplane, lda, m0, Bm, Bplane, ldb, n0, 64, tid);

    for (int ci = 0; ci < nc; ci++) {
        if (ci + 1 < nc) { CP_WAIT(1); } else { CP_WAIT(0); }
        __syncthreads();

        u32 sb = sbase + (u32)(ci & 1) * 65536u;
        #pragma unroll
        for (int ks = 0; ks < 4; ks++) {
            u32 afr[2][2][4];                                  // [plane][mh][4]
            #pragma unroll
            for (int p = 0; p < 2; p++)
                #pragma unroll
                for (int mh = 0; mh < 2; mh++) {
                    int row = wm * 32 + mh * 16 + ph_row;
                    u32 ad = sb + (u32)p * 16384u + swz((u32)(row * 128 + ks * 32 + ph_byte));
                    ldsm4(ad, afr[p][mh][0], afr[p][mh][1], afr[p][mh][2], afr[p][mh][3]);
                }
            u32 bfr[2][4][4];                                  // [plane][nq16][4]
            #pragma unroll
            for (int p = 0; p < 2; p++)
                #pragma unroll
                for (int nq = 0; nq < 4; nq++) {
                    int row = wn * 64 + nq * 16 + ph_row;
                    u32 ad = sb + 32768u + (u32)p * 16384u + swz((u32)(row * 128 + ks * 32 + ph_byte));
                    ldsm4(ad, bfr[p][nq][0], bfr[p][nq][1], bfr[p][nq][2], bfr[p][nq][3]);
                }
            // combo 0: Ahi*Bhi, combo 1: Ahi*Blo, combo 2: Alo*Bhi
            #pragma unroll
            for (int cb = 0; cb < 3; cb++) {
                const int pa = (cb == 2) ? 1 : 0;
                const int pb = (cb == 1) ? 1 : 0;
                #pragma unroll
                for (int mh = 0; mh < 2; mh++)
                    #pragma unroll
                    for (int nq = 0; nq < 4; nq++) {
                        mma16816(acc[mh][nq * 2 + 0], afr[pa][mh], bfr[pb][nq][0], bfr[pb][nq][2]);
                        mma16816(acc[mh][nq * 2 + 1], afr[pa][mh], bfr[pb][nq][1], bfr[pb][nq][3]);
                    }
            }
        }
        __syncthreads();
        if (ci + 2 < nc)
            stage_load(sbase, ci & 1, A, Aplane, lda, m0, Bm, Bplane, ldb, n0,
                       (long long)(ci + 2) * 64, tid);
    }

    // epilogue: d-frag lane map: (r = lane>>2 [+8], c = (lane&3)*2 [+1])
    __nv_bfloat16* Cl = Ch + Cplane;
    #pragma unroll
    for (int mh = 0; mh < 2; mh++)
        #pragma unroll
        for (int nf = 0; nf < 8; nf++) {
            float* c = acc[mh][nf];
            long long mA = m0 + wm * 32 + mh * 16 + (lane >> 2);
            long long nA = n0 + wn * 64 + nf * 8 + (lane & 3) * 2;
            #pragma unroll
            for (int q = 0; q < 4; q++) {
                long long m = mA + (q >> 1) * 8;
                long long n = nA + (q & 1);
                float v = alpha * c[q];
                long long co = Cb + m * Crs + n * Ccs;
                if (outSplit) {
                    __nv_bfloat16 hi = __float2bfloat16(v);
                    Ch[co] = hi;
                    Cl[co] = __float2bfloat16(v - __bfloat162float(hi));
                } else {
                    Cf[co] = v;
                }
            }
        }
}

// ---------------- fp32 -> split bf16 conversion ----------------
__global__ __launch_bounds__(256) void split_kernel(const float* __restrict__ x,
                                                    __nv_bfloat16* __restrict__ hi,
                                                    long long n, long long plane) {
    long long i = (long long)blockIdx.x * 256 + threadIdx.x;   // float4 units
    if (i * 4 >= n) return;
    float4 v = ((const float4*)x)[i];
    __nv_bfloat16* lo = hi + plane;
    __nv_bfloat16 h0 = __float2bfloat16(v.x), h1 = __float2bfloat16(v.y);
    __nv_bfloat16 h2 = __float2bfloat16(v.z), h3 = __float2bfloat16(v.w);
    ((__nv_bfloat162*)hi)[2 * i]     = __halves2bfloat162(h0, h1);
    ((__nv_bfloat162*)hi)[2 * i + 1] = __halves2bfloat162(h2, h3);
    __nv_bfloat16 l0 = __float2bfloat16(v.x - __bfloat162float(h0));
    __nv_bfloat16 l1 = __float2bfloat16(v.y - __bfloat162float(h1));
    __nv_bfloat16 l2 = __float2bfloat16(v.z - __bfloat162float(h2));
    __nv_bfloat16 l3 = __float2bfloat16(v.w - __bfloat162float(h3));
    ((__nv_bfloat162*)lo)[2 * i]     = __halves2bfloat162(l0, l1);
    ((__nv_bfloat162*)lo)[2 * i + 1] = __halves2bfloat162(l2, l3);
}

// ---------------- block reductions ----------------
__device__ __forceinline__ float blockReduceSum(float v) {
    __shared__ float sh[33];
    __syncthreads();
    #pragma unroll
    for (int o = 16; o; o >>= 1) v += __shfl_xor_sync(0xffffffffu, v, o);
    if ((threadIdx.x & 31) == 0) sh[threadIdx.x >> 5] = v;
    __syncthreads();
    if (threadIdx.x < 32) {
        v = (threadIdx.x < (blockDim.x >> 5)) ? sh[threadIdx.x] : 0.f;
        #pragma unroll
        for (int o = 16; o; o >>= 1) v += __shfl_xor_sync(0xffffffffu, v, o);
        if (threadIdx.x == 0) sh[32] = v;
    }
    __syncthreads();
    return sh[32];
}
__device__ __forceinline__ float blockReduceMax(float v) {
    __shared__ float sh[33];
    __syncthreads();
    #pragma unroll
    for (int o = 16; o; o >>= 1) v = fmaxf(v, __shfl_xor_sync(0xffffffffu, v, o));
    if ((threadIdx.x & 31) == 0) sh[threadIdx.x >> 5] = v;
    __syncthreads();
    if (threadIdx.x < 32) {
        v = (threadIdx.x < (blockDim.x >> 5)) ? sh[threadIdx.x] : -INFINITY;
        #pragma unroll
        for (int o = 16; o; o >>= 1) v = fmaxf(v, __shfl_xor_sync(0xffffffffu, v, o));
        if (threadIdx.x == 0) sh[32] = v;
    }
    __syncthreads();
    return sh[32];
}

// ---------------- mag1 / v3 ----------------
__global__ __launch_bounds__(256) void mag_kernel(const float* __restrict__ emb) {
    int row = blockIdx.x;
    int tid = threadIdx.x;
    float v = emb[(long long)row * D_ + HD_ + tid];
    float ss = blockReduceSum(v * v);
    if (tid == 0) {
        g_mag1[row] = sqrtf(ss);
        g_v3[row]   = emb[(long long)row * D_ + (D_ - 1)];
    }
}
__global__ __launch_bounds__(256) void mean_kernel() {
    int tid = threadIdx.x;
    float acc = 0.f;
    for (int b = 0; b < B_; b++) {
        float v = 0.f;
        for (int i = tid; i < S_; i += 256) v += g_mag1[b * S_ + i];
        v = blockReduceSum(v);
        acc += v * v;
    }
    if (tid == 0) g_mean = acc / ((float)B_ * (float)S_ * (float)S_);
}

// ---------------- bias + softmax: g_S -> split bf16 weights ----------------
__global__ __launch_bounds__(256) void softmax_kernel(const float* __restrict__ bias_scalars) {
    int s = blockIdx.x, h = blockIdx.y, b = blockIdx.z;
    int tid = threadIdx.x;
    const long long roff = (((long long)(b * H_ + h)) * S_ + s) * S_;
    const float* row = g_S + roff;
    __nv_bfloat16* whi = g_Ws + roff;
    __nv_bfloat16* wlo = g_Ws + (size_t)B_ * H_ * S_ * S_ + roff;
    float bs = bias_scalars[h];
    float mean = g_mean;
    float ms = g_mag1[b * S_ + s];
    float vs = g_v3[b * S_ + s];

    float vals[8];
    #pragma unroll
    for (int i = 0; i < 8; i++) {
        int t = tid + i * 256;
        float x = row[t];
        float bias;
        if (h == 0)      bias = (t > s) ? bs : 0.f;
        else if (h == 1) bias = (ms * g_mag1[b * S_ + t] > mean) ? bs : 0.f;
        else if (h == 2) bias = expf(fabsf((float)(t - s)) * (-1.f / (float)S_)) * bs;
        else             bias = (vs * g_v3[b * S_ + t] > 0.5f) ? bs : 0.f;
        vals[i] = x + bias;
    }
    float m = -INFINITY;
    #pragma unroll
    for (int i = 0; i < 8; i++) m = fmaxf(m, vals[i]);
    m = blockReduceMax(m);
    float sum = 0.f;
    #pragma unroll
    for (int i = 0; i < 8; i++) { vals[i] = expf(vals[i] - m); sum += vals[i]; }
    sum = blockReduceSum(sum);
    float inv = 1.f / sum;
    #pragma unroll
    for (int i = 0; i < 8; i++) {
        int t = tid + i * 256;
        float w = vals[i] * inv;
        __nv_bfloat16 hi = __float2bfloat16(w);
        whi[t] = hi;
        wlo[t] = __float2bfloat16(w - __bfloat162float(hi));
    }
}

// ---------------- head-average of split weights -> output region 1 ----------------
__global__ __launch_bounds__(256) void avg_kernel(float* __restrict__ outAvg) {
    long long idx = (long long)blockIdx.x * 256 + threadIdx.x;   // bf162 units
    const long long bq = (long long)S_ * S_ / 2;
    int b = (int)(idx / bq);
    long long r = idx - (long long)b * bq;
    const __nv_bfloat162* hi = (const __nv_bfloat162*)g_Ws;
    const __nv_bfloat162* lo = (const __nv_bfloat162*)(g_Ws + (size_t)B_ * H_ * S_ * S_);
    float sx = 0.f, sy = 0.f;
    #pragma unroll
    for (int h = 0; h < H_; h++) {
        long long o = ((long long)(b * H_ + h)) * bq + r;
        __nv_bfloat162 a = hi[o], c = lo[o];
        sx += __bfloat162float(a.x) + __bfloat162float(c.x);
        sy += __bfloat162float(a.y) + __bfloat162float(c.y);
    }
    ((float2*)outAvg)[idx] = make_float2(0.25f * sx, 0.25f * sy);
}

__global__ void guilt_kernel(float* __restrict__ outG) {
    int i = blockIdx.x * 256 + threadIdx.x;
    if (i < B_ * S_) outG[i] = 1.0f / (float)S_;
}

// ---------------- bias + residual + LayerNorm ----------------
__global__ __launch_bounds__(256) void ln_kernel(const float* __restrict__ emb,
                                                 const float* __restrict__ Wo_b,
                                                 const float* __restrict__ gam,
                                                 const float* __restrict__ bet,
                                                 float* __restrict__ outp) {
    int tok = blockIdx.x;
    int tid = threadIdx.x;
    float y[4];
    float s1 = 0.f;
    #pragma unroll
    for (int i = 0; i < 4; i++) {
        int d = tid + i * 256;
        y[i] = g_wo[(long long)tok * D_ + d] + Wo_b[d] + emb[(long long)tok * D_ + d];
        s1 += y[i];
    }
    s1 = blockReduceSum(s1);
    float mu = s1 * (1.f / (float)D_);
    float s2 = 0.f;
    #pragma unroll
    for (int i = 0; i < 4; i++) { float dd = y[i] - mu; s2 += dd * dd; }
    s2 = blockReduceSum(s2);
    float inv = rsqrtf(s2 * (1.f / (float)D_) + LN_EPS);
    #pragma unroll
    for (int i = 0; i < 4; i++) {
        int d = tid + i * 256;
        outp[(long long)tok * D_ + d] = (y[i] - mu) * inv * gam[d] + bet[d];
    }
}

// ---------------- launch ----------------
extern "C" void kernel_launch(void* const* d_in, const int* in_sizes, int n_in,
                              void* d_out, int out_size) {
    const float* emb   = (const float*)d_in[0];
    const float* Wq    = (const float*)d_in[1];
    const float* Wk    = (const float*)d_in[2];
    const float* Wv    = (const float*)d_in[3];
    const float* bsc   = (const float*)d_in[4];
    const float* Wo_w  = (const float*)d_in[5];
    const float* Wo_b  = (const float*)d_in[6];
    const float* ln_g  = (const float*)d_in[7];
    const float* ln_b  = (const float*)d_in[8];
    float* out = (float*)d_out;

    float *pS, *pWo;
    __nv_bfloat16 *pWs, *pQs, *pKs, *pVts, *pEs, *pWqs, *pWks, *pWvs, *pWos, *pCs;
    cudaGetSymbolAddress((void**)&pS,   g_S);
    cudaGetSymbolAddress((void**)&pWs,  g_Ws);
    cudaGetSymbolAddress((void**)&pQs,  g_Qs);
    cudaGetSymbolAddress((void**)&pKs,  g_Ks);
    cudaGetSymbolAddress((void**)&pVts, g_Vts);
    cudaGetSymbolAddress((void**)&pEs,  g_embs);
    cudaGetSymbolAddress((void**)&pWqs, g_Wqs);
    cudaGetSymbolAddress((void**)&pWks, g_Wks);
    cudaGetSymbolAddress((void**)&pWvs, g_Wvs);
    cudaGetSymbolAddress((void**)&pWos, g_Wos);
    cudaGetSymbolAddress((void**)&pCs,  g_Cs);
    cudaGetSymbolAddress((void**)&pWo,  g_wo);

    const long long SD  = (long long)S_ * D_;
    const long long SH  = (long long)S_ * HD_;
    const long long SS  = (long long)S_ * S_;
    const long long EP  = (long long)B_ * SD;          // emb plane
    const long long QP  = (long long)B_ * H_ * SH;     // Q/K/Vt plane
    const long long WP  = (long long)B_ * H_ * SS;     // weights plane
    const long long WQP = (long long)H_ * HD_ * HD_;
    const long long WOP = (long long)D_ * D_;

    const int DSMEM = 131072;   // 2 x 64KB stages
    cudaFuncSetAttribute(mma_gemm, cudaFuncAttributeMaxDynamicSharedMemorySize, DSMEM);

    dim3 blk(256);

    // conversions to split bf16
    split_kernel<<<(unsigned)(EP / 4 / 256), blk>>>(emb, pEs, EP, EP);
    split_kernel<<<(unsigned)(WQP / 4 / 256), blk>>>(Wq, pWqs, WQP, WQP);
    split_kernel<<<(unsigned)(WQP / 4 / 256), blk>>>(Wk, pWks, WQP, WQP);
    split_kernel<<<(unsigned)(WQP / 4 / 256), blk>>>(Wv, pWvs, WQP, WQP);
    split_kernel<<<(unsigned)(WOP / 4 / 256), blk>>>(Wo_w, pWos, WOP, WOP);

    // Q = X @ Wq^T  -> split planes, row-major [b,h,s,e]
    mma_gemm<<<dim3(2, 16, 16), blk, DSMEM>>>(pEs, EP, D_, SD, HD_,
        pWqs, WQP, HD_, 0, (long long)HD_ * HD_,
        pS /*unused*/, pQs, QP, (long long)H_ * SH, SH, HD_, 1, HD_, 1.0f, H_, 1);
    // K
    mma_gemm<<<dim3(2, 16, 16), blk, DSMEM>>>(pEs, EP, D_, SD, HD_,
        pWks, WQP, HD_, 0, (long long)HD_ * HD_,
        pS, pKs, QP, (long long)H_ * SH, SH, HD_, 1, HD_, 1.0f, H_, 1);
    // V, stored transposed [b,h,e,t]
    mma_gemm<<<dim3(2, 16, 16), blk, DSMEM>>>(pEs, EP, D_, SD, HD_,
        pWvs, WQP, HD_, 0, (long long)HD_ * HD_,
        pS, pVts, QP, (long long)H_ * HD_ * S_, (long long)HD_ * S_, 1, S_, HD_, 1.0f, H_, 1);

    // mag1 / v3 / intent mean
    mag_kernel<<<B_ * S_, blk>>>(emb);
    mean_kernel<<<1, blk>>>();

    // scores = (Q @ K^T) / 16 -> fp32 g_S
    mma_gemm<<<dim3(16, 16, 16), blk, DSMEM>>>(pQs, QP, HD_, (long long)H_ * SH, SH,
        pKs, QP, HD_, (long long)H_ * SH, SH,
        pS, pQs /*unused*/, 0, (long long)H_ * SS, SS, S_, 1, HD_, 0.0625f, H_, 0);

    // + biases, softmax -> split bf16 weights
    softmax_kernel<<<dim3(S_, H_, B_), blk>>>(bsc);

    // average weights + guilt -> output regions 1 & 2
    avg_kernel<<<(unsigned)((long long)B_ * SS / 2 / 256), blk>>>(out + EP);
    guilt_kernel<<<(B_ * S_ + 255) / 256, blk>>>(out + EP + (long long)B_ * SS);

    // attended = W @ V -> concat split bf16 [b,s,h*hd+e]
    mma_gemm<<<dim3(2, 16, 16), blk, DSMEM>>>(pWs, WP, S_, (long long)H_ * SS, SS,
        pVts, QP, S_, (long long)H_ * HD_ * S_, (long long)HD_ * S_,
        pS, pCs, EP, SD, HD_, D_, 1, S_, 1.0f, H_, 1);

    // out_pre = concat @ Wo^T -> fp32 g_wo
    mma_gemm<<<dim3(8, 64, 1), blk, DSMEM>>>(pCs, EP, D_, 0, 0,
        pWos, WOP, D_, 0, 0,
        pWo, pCs /*unused*/, 0, 0, 0, D_, 1, D_, 1.0f, 1, 0);

    // + Wo_b + residual + LayerNorm -> output region 0
    ln_kernel<<<B_ * S_, blk>>>(emb, Wo_b, ln_g, ln_b, out);
}

// round 6
// speedup vs baseline: 2.2647x; 1.1760x over previous
#include <cuda_runtime.h>
#include <cuda_bf16.h>
#include <math.h>

#define B_  4
#define S_  2048
#define D_  1024
#define H_  4
#define HD_ 256
#define LN_EPS 1e-5f

typedef unsigned int       u32;
typedef unsigned long long u64;

// ---------------- device scratch (no cudaMalloc allowed) ----------------
// split bf16 arrays: hi plane at [0, N), lo plane at [N, 2N)
__device__ __align__(16) float          g_S [(size_t)B_*H_*S_*S_];     // fp32 scores
__device__ __align__(16) __nv_bfloat16  g_Ws[2*(size_t)B_*H_*S_*S_];   // softmax weights split
__device__ __align__(16) __nv_bfloat16  g_Qs[2*(size_t)B_*H_*S_*HD_];
__device__ __align__(16) __nv_bfloat16  g_Ks[2*(size_t)B_*H_*S_*HD_];
__device__ __align__(16) __nv_bfloat16  g_Vts[2*(size_t)B_*H_*HD_*S_]; // V transposed [b,h,e,t]
__device__ __align__(16) __nv_bfloat16  g_embs[2*(size_t)B_*S_*D_];
__device__ __align__(16) __nv_bfloat16  g_Wqs[2*(size_t)H_*HD_*HD_];
__device__ __align__(16) __nv_bfloat16  g_Wks[2*(size_t)H_*HD_*HD_];
__device__ __align__(16) __nv_bfloat16  g_Wvs[2*(size_t)H_*HD_*HD_];
__device__ __align__(16) __nv_bfloat16  g_Wos[2*(size_t)D_*D_];
__device__ __align__(16) __nv_bfloat16  g_Cs[(size_t)B_*S_*D_];        // concat (hi only)
__device__ __align__(16) float          g_wo[(size_t)B_*S_*D_];        // Wo output pre-LN
__device__ float g_mag1[B_*S_];
__device__ float g_v3[B_*S_];
__device__ float g_mean;

// ---------------- helpers ----------------
__device__ __forceinline__ u32 smem_to_u32(const void* p) {
    u32 a;
    asm("{ .reg .u64 t; cvta.to.shared.u64 t, %1; cvt.u32.u64 %0, t; }" : "=r"(a) : "l"(p));
    return a;
}
static __device__ __forceinline__ u32 swz(u32 o) { return o ^ ((o >> 3) & 0x70u); }

__device__ __forceinline__ void cp_async16(u32 dst, const void* src) {
    asm volatile("cp.async.cg.shared.global [%0], [%1], 16;" :: "r"(dst), "l"(src));
}
#define CP_COMMIT()  asm volatile("cp.async.commit_group;" ::: "memory")
#define CP_WAIT(N)   asm volatile("cp.async.wait_group %0;" :: "n"(N) : "memory")

__device__ __forceinline__ void ldsm4(u32 addr, u32& r0, u32& r1, u32& r2, u32& r3) {
    asm volatile("ldmatrix.sync.aligned.m8n8.x4.shared.b16 {%0,%1,%2,%3}, [%4];"
        : "=r"(r0), "=r"(r1), "=r"(r2), "=r"(r3) : "r"(addr));
}
__device__ __forceinline__ void mma16816(float* c, const u32* a, u32 b0, u32 b1) {
    asm volatile("mma.sync.aligned.m16n8k16.row.col.f32.bf16.bf16.f32 "
        "{%0,%1,%2,%3}, {%4,%5,%6,%7}, {%8,%9}, {%0,%1,%2,%3};"
        : "+f"(c[0]), "+f"(c[1]), "+f"(c[2]), "+f"(c[3])
        : "r"(a[0]), "r"(a[1]), "r"(a[2]), "r"(a[3]), "r"(b0), "r"(b1));
}

// ============================================================================
// Generic batched NT GEMM via mma.sync: C = alpha * (A @ B^T), split-bf16.
// A: hi plane at A, (lo at A+Aplane if aLo); B always hi+lo planes.
// Combos: Ahi*Bhi + Ahi*Blo (+ Alo*Bhi if aLo).
// CTA tile 128x128, K-chunk 64. 2-stage cp.async pipeline (2 x 64KB smem).
// Stage layout: Ahi @0, Alo @16K (may be unused), Bhi @32K, Blo @48K. SW128.
// Output: outMode 0 = fp32 Cf; 1 = split bf16 (Ch, Ch+Cplane); 2 = bf16 hi only.
// ============================================================================
__device__ __forceinline__ void stage_load(u32 sbase, int buf,
    const __nv_bfloat16* A, long long Aplane, int lda, int m0,
    const __nv_bfloat16* Bm, long long Bplane, int ldb, int n0,
    long long kof, int tid, int aLo)
{
    #pragma unroll
    for (int it = 0; it < 16; it++) {
        int idx = tid + it * 256;
        int tile = idx >> 10;                // 0 Ahi, 1 Alo, 2 Bhi, 3 Blo
        if (tile == 1 && !aLo) continue;
        int rem = idx & 1023;
        int r = rem >> 3, c = rem & 7;
        const __nv_bfloat16* src;
        if (tile < 2)
            src = A + (long long)tile * Aplane + (long long)(m0 + r) * lda + kof + c * 8;
        else
            src = Bm + (long long)(tile - 2) * Bplane + (long long)(n0 + r) * ldb + kof + c * 8;
        u32 dst = sbase + (u32)buf * 65536u + (u32)tile * 16384u + swz((u32)(r * 128 + c * 16));
        cp_async16(dst, src);
    }
    CP_COMMIT();
}

__global__ void __launch_bounds__(256, 1)
mma_gemm(const __nv_bfloat16* __restrict__ A, long long Aplane, int lda,
         long long Asb, long long Ash,
         const __nv_bfloat16* __restrict__ Bm, long long Bplane, int ldb,
         long long Bsb, long long Bsh,
         float* __restrict__ Cf, __nv_bfloat16* __restrict__ Ch, long long Cplane,
         long long Csb, long long Csh, long long Crs, long long Ccs,
         int K, float alpha, int Hdiv, int outMode, int aLo)
{
    extern __shared__ __align__(16) char smem[];
    const u32 sbase = smem_to_u32(smem);

    int tid = threadIdx.x, lane = tid & 31, wid = tid >> 5;
    int wm = wid & 3, wn = wid >> 2;                 // warp tile 32x64 at (wm*32, wn*64)
    int z = blockIdx.z, b = z / Hdiv, h = z % Hdiv;
    A  += b * Asb + h * Ash;
    Bm += b * Bsb + h * Bsh;
    const long long Cb = b * Csb + h * Csh;

    const int m0 = blockIdx.y * 128, n0 = blockIdx.x * 128;

    // ldmatrix per-lane addressing (row within 16, byte half of k16-step)
    const int ph_row  = (lane & 7) + ((lane >> 3) & 1) * 8;
    const int ph_byte = (lane >> 4) * 16;

    float acc[2][8][4];
    #pragma unroll
    for (int i = 0; i < 2; i++)
        #pragma unroll
        for (int j = 0; j < 8; j++)
            #pragma unroll
            for (int k = 0; k < 4; k++) acc[i][j][k] = 0.f;

    const int nc = K >> 6;
    stage_load(sbase, 0, A, Aplane, lda, m0, Bm, Bplane, ldb, n0, 0,  tid, aLo);
    stage_load(sbase, 1, A, Aplane, lda, m0, Bm, Bplane, ldb, n0, 64, tid, aLo);

    for (int ci = 0; ci < nc; ci++) {
        if (ci + 1 < nc) { CP_WAIT(1); } else { CP_WAIT(0); }
        __syncthreads();

        u32 sb = sbase + (u32)(ci & 1) * 65536u;
        #pragma unroll
        for (int ks = 0; ks < 4; ks++) {
            u32 afr[2][2][4];                                  // [plane][mh][4]
            #pragma unroll
            for (int mh = 0; mh < 2; mh++) {
                int row = wm * 32 + mh * 16 + ph_row;
                u32 ad = sb + swz((u32)(row * 128 + ks * 32 + ph_byte));
                ldsm4(ad, afr[0][mh][0], afr[0][mh][1], afr[0][mh][2], afr[0][mh][3]);
            }
            if (aLo) {
                #pragma unroll
                for (int mh = 0; mh < 2; mh++) {
                    int row = wm * 32 + mh * 16 + ph_row;
                    u32 ad = sb + 16384u + swz((u32)(row * 128 + ks * 32 + ph_byte));
                    ldsm4(ad, afr[1][mh][0], afr[1][mh][1], afr[1][mh][2], afr[1][mh][3]);
                }
            }
            u32 bfr[2][4][4];                                  // [plane][nq16][4]
            #pragma unroll
            for (int p = 0; p < 2; p++)
                #pragma unroll
                for (int nq = 0; nq < 4; nq++) {
                    int row = wn * 64 + nq * 16 + ph_row;
                    u32 ad = sb + 32768u + (u32)p * 16384u + swz((u32)(row * 128 + ks * 32 + ph_byte));
                    ldsm4(ad, bfr[p][nq][0], bfr[p][nq][1], bfr[p][nq][2], bfr[p][nq][3]);
                }
            // combo 0: Ahi*Bhi, combo 1: Ahi*Blo
            #pragma unroll
            for (int cb = 0; cb < 2; cb++) {
                const int pb = cb;
                #pragma unroll
                for (int mh = 0; mh < 2; mh++)
                    #pragma unroll
                    for (int nq = 0; nq < 4; nq++) {
                        mma16816(acc[mh][nq * 2 + 0], afr[0][mh], bfr[pb][nq][0], bfr[pb][nq][2]);
                        mma16816(acc[mh][nq * 2 + 1], afr[0][mh], bfr[pb][nq][1], bfr[pb][nq][3]);
                    }
            }
            if (aLo) {                                         // combo 2: Alo*Bhi
                #pragma unroll
                for (int mh = 0; mh < 2; mh++)
                    #pragma unroll
                    for (int nq = 0; nq < 4; nq++) {
                        mma16816(acc[mh][nq * 2 + 0], afr[1][mh], bfr[0][nq][0], bfr[0][nq][2]);
                        mma16816(acc[mh][nq * 2 + 1], afr[1][mh], bfr[0][nq][1], bfr[0][nq][3]);
                    }
            }
        }
        __syncthreads();
        if (ci + 2 < nc)
            stage_load(sbase, ci & 1, A, Aplane, lda, m0, Bm, Bplane, ldb, n0,
                       (long long)(ci + 2) * 64, tid, aLo);
    }

    // epilogue: d-frag lane map: (r = lane>>2 [+8], c = (lane&3)*2 [+1])
    __nv_bfloat16* Cl = Ch + Cplane;
    #pragma unroll
    for (int mh = 0; mh < 2; mh++)
        #pragma unroll
        for (int nf = 0; nf < 8; nf++) {
            float* c = acc[mh][nf];
            long long mA = m0 + wm * 32 + mh * 16 + (lane >> 2);
            long long nA = n0 + wn * 64 + nf * 8 + (lane & 3) * 2;
            #pragma unroll
            for (int q = 0; q < 4; q++) {
                long long m = mA + (q >> 1) * 8;
                long long n = nA + (q & 1);
                float v = alpha * c[q];
                long long co = Cb + m * Crs + n * Ccs;
                if (outMode == 0) {
                    Cf[co] = v;
                } else if (outMode == 1) {
                    __nv_bfloat16 hi = __float2bfloat16(v);
                    Ch[co] = hi;
                    Cl[co] = __float2bfloat16(v - __bfloat162float(hi));
                } else {
                    Ch[co] = __float2bfloat16(v);
                }
            }
        }
}

// ---------------- fp32 -> split bf16 conversion ----------------
__global__ __launch_bounds__(256) void split_kernel(const float* __restrict__ x,
                                                    __nv_bfloat16* __restrict__ hi,
                                                    long long n, long long plane) {
    long long i = (long long)blockIdx.x * 256 + threadIdx.x;   // float4 units
    if (i * 4 >= n) return;
    float4 v = ((const float4*)x)[i];
    __nv_bfloat16* lo = hi + plane;
    __nv_bfloat16 h0 = __float2bfloat16(v.x), h1 = __float2bfloat16(v.y);
    __nv_bfloat16 h2 = __float2bfloat16(v.z), h3 = __float2bfloat16(v.w);
    ((__nv_bfloat162*)hi)[2 * i]     = __halves2bfloat162(h0, h1);
    ((__nv_bfloat162*)hi)[2 * i + 1] = __halves2bfloat162(h2, h3);
    __nv_bfloat16 l0 = __float2bfloat16(v.x - __bfloat162float(h0));
    __nv_bfloat16 l1 = __float2bfloat16(v.y - __bfloat162float(h1));
    __nv_bfloat16 l2 = __float2bfloat16(v.z - __bfloat162float(h2));
    __nv_bfloat16 l3 = __float2bfloat16(v.w - __bfloat162float(h3));
    ((__nv_bfloat162*)lo)[2 * i]     = __halves2bfloat162(l0, l1);
    ((__nv_bfloat162*)lo)[2 * i + 1] = __halves2bfloat162(l2, l3);
}

// ---------------- block reductions ----------------
__device__ __forceinline__ float blockReduceSum(float v) {
    __shared__ float sh[33];
    __syncthreads();
    #pragma unroll
    for (int o = 16; o; o >>= 1) v += __shfl_xor_sync(0xffffffffu, v, o);
    if ((threadIdx.x & 31) == 0) sh[threadIdx.x >> 5] = v;
    __syncthreads();
    if (threadIdx.x < 32) {
        v = (threadIdx.x < (blockDim.x >> 5)) ? sh[threadIdx.x] : 0.f;
        #pragma unroll
        for (int o = 16; o; o >>= 1) v += __shfl_xor_sync(0xffffffffu, v, o);
        if (threadIdx.x == 0) sh[32] = v;
    }
    __syncthreads();
    return sh[32];
}
__device__ __forceinline__ float blockReduceMax(float v) {
    __shared__ float sh[33];
    __syncthreads();
    #pragma unroll
    for (int o = 16; o; o >>= 1) v = fmaxf(v, __shfl_xor_sync(0xffffffffu, v, o));
    if ((threadIdx.x & 31) == 0) sh[threadIdx.x >> 5] = v;
    __syncthreads();
    if (threadIdx.x < 32) {
        v = (threadIdx.x < (blockDim.x >> 5)) ? sh[threadIdx.x] : -INFINITY;
        #pragma unroll
        for (int o = 16; o; o >>= 1) v = fmaxf(v, __shfl_xor_sync(0xffffffffu, v, o));
        if (threadIdx.x == 0) sh[32] = v;
    }
    __syncthreads();
    return sh[32];
}

// ---------------- mag1 / v3 ----------------
__global__ __launch_bounds__(256) void mag_kernel(const float* __restrict__ emb) {
    int row = blockIdx.x;
    int tid = threadIdx.x;
    float v = emb[(long long)row * D_ + HD_ + tid];
    float ss = blockReduceSum(v * v);
    if (tid == 0) {
        g_mag1[row] = sqrtf(ss);
        g_v3[row]   = emb[(long long)row * D_ + (D_ - 1)];
    }
}
__global__ __launch_bounds__(256) void mean_kernel() {
    int tid = threadIdx.x;
    float acc = 0.f;
    for (int b = 0; b < B_; b++) {
        float v = 0.f;
        for (int i = tid; i < S_; i += 256) v += g_mag1[b * S_ + i];
        v = blockReduceSum(v);
        acc += v * v;
    }
    if (tid == 0) g_mean = acc / ((float)B_ * (float)S_ * (float)S_);
}

// ---------------- bias + softmax: g_S -> split bf16 weights ----------------
__global__ __launch_bounds__(256) void softmax_kernel(const float* __restrict__ bias_scalars) {
    int s = blockIdx.x, h = blockIdx.y, b = blockIdx.z;
    int tid = threadIdx.x;
    const long long roff = (((long long)(b * H_ + h)) * S_ + s) * S_;
    const float4* row4 = (const float4*)(g_S + roff);
    __nv_bfloat162* whi2 = (__nv_bfloat162*)(g_Ws + roff);
    __nv_bfloat162* wlo2 = (__nv_bfloat162*)(g_Ws + (size_t)B_ * H_ * S_ * S_ + roff);
    float bs = bias_scalars[h];
    float mean = g_mean;
    float ms = g_mag1[b * S_ + s];
    float vs = g_v3[b * S_ + s];

    float vals[8];
    #pragma unroll
    for (int i = 0; i < 2; i++) {
        int j = tid + i * 256;
        float4 x = row4[j];
        int t0 = 4 * j;
        float* vv = vals + i * 4;
        vv[0] = x.x; vv[1] = x.y; vv[2] = x.z; vv[3] = x.w;
        #pragma unroll
        for (int q = 0; q < 4; q++) {
            int t = t0 + q;
            float bias;
            if (h == 0)      bias = (t > s) ? bs : 0.f;
            else if (h == 1) bias = (ms * g_mag1[b * S_ + t] > mean) ? bs : 0.f;
            else if (h == 2) bias = expf(fabsf((float)(t - s)) * (-1.f / (float)S_)) * bs;
            else             bias = (vs * g_v3[b * S_ + t] > 0.5f) ? bs : 0.f;
            vv[q] += bias;
        }
    }
    float m = -INFINITY;
    #pragma unroll
    for (int i = 0; i < 8; i++) m = fmaxf(m, vals[i]);
    m = blockReduceMax(m);
    float sum = 0.f;
    #pragma unroll
    for (int i = 0; i < 8; i++) { vals[i] = expf(vals[i] - m); sum += vals[i]; }
    sum = blockReduceSum(sum);
    float inv = 1.f / sum;
    #pragma unroll
    for (int i = 0; i < 2; i++) {
        int j = tid + i * 256;
        float w0 = vals[i * 4 + 0] * inv, w1 = vals[i * 4 + 1] * inv;
        float w2 = vals[i * 4 + 2] * inv, w3 = vals[i * 4 + 3] * inv;
        __nv_bfloat16 h0 = __float2bfloat16(w0), h1 = __float2bfloat16(w1);
        __nv_bfloat16 h2 = __float2bfloat16(w2), h3 = __float2bfloat16(w3);
        whi2[2 * j]     = __halves2bfloat162(h0, h1);
        whi2[2 * j + 1] = __halves2bfloat162(h2, h3);
        __nv_bfloat16 l0 = __float2bfloat16(w0 - __bfloat162float(h0));
        __nv_bfloat16 l1 = __float2bfloat16(w1 - __bfloat162float(h1));
        __nv_bfloat16 l2 = __float2bfloat16(w2 - __bfloat162float(h2));
        __nv_bfloat16 l3 = __float2bfloat16(w3 - __bfloat162float(h3));
        wlo2[2 * j]     = __halves2bfloat162(l0, l1);
        wlo2[2 * j + 1] = __halves2bfloat162(l2, l3);
    }
}

// ---------------- head-average of split weights -> output region 1 ----------------
__global__ __launch_bounds__(256) void avg_kernel(float* __restrict__ outAvg) {
    long long idx = (long long)blockIdx.x * 256 + threadIdx.x;   // 8-element groups
    const long long bq = (long long)S_ * S_ / 8;
    int b = (int)(idx / bq);
    long long r = idx - (long long)b * bq;
    const uint4* hi = (const uint4*)g_Ws;
    const uint4* lo = (const uint4*)(g_Ws + (size_t)B_ * H_ * S_ * S_);
    float acc[8];
    #pragma unroll
    for (int q = 0; q < 8; q++) acc[q] = 0.f;
    #pragma unroll
    for (int h = 0; h < H_; h++) {
        long long o = ((long long)(b * H_ + h)) * bq + r;
        uint4 a = hi[o], c = lo[o];
        const u32 ar[4] = {a.x, a.y, a.z, a.w};
        const u32 cr[4] = {c.x, c.y, c.z, c.w};
        #pragma unroll
        for (int p = 0; p < 4; p++) {
            float2 fa = __bfloat1622float2(*(const __nv_bfloat162*)&ar[p]);
            float2 fc = __bfloat1622float2(*(const __nv_bfloat162*)&cr[p]);
            acc[2 * p]     += fa.x + fc.x;
            acc[2 * p + 1] += fa.y + fc.y;
        }
    }
    float4 o0 = make_float4(0.25f * acc[0], 0.25f * acc[1], 0.25f * acc[2], 0.25f * acc[3]);
    float4 o1 = make_float4(0.25f * acc[4], 0.25f * acc[5], 0.25f * acc[6], 0.25f * acc[7]);
    ((float4*)outAvg)[2 * idx]     = o0;
    ((float4*)outAvg)[2 * idx + 1] = o1;
}

__global__ void guilt_kernel(float* __restrict__ outG) {
    int i = blockIdx.x * 256 + threadIdx.x;
    if (i < B_ * S_) outG[i] = 1.0f / (float)S_;
}

// ---------------- bias + residual + LayerNorm ----------------
__global__ __launch_bounds__(256) void ln_kernel(const float* __restrict__ emb,
                                                 const float* __restrict__ Wo_b,
                                                 const float* __restrict__ gam,
                                                 const float* __restrict__ bet,
                                                 float* __restrict__ outp) {
    int tok = blockIdx.x;
    int tid = threadIdx.x;
    float y[4];
    float s1 = 0.f;
    #pragma unroll
    for (int i = 0; i < 4; i++) {
        int d = tid + i * 256;
        y[i] = g_wo[(long long)tok * D_ + d] + Wo_b[d] + emb[(long long)tok * D_ + d];
        s1 += y[i];
    }
    s1 = blockReduceSum(s1);
    float mu = s1 * (1.f / (float)D_);
    float s2 = 0.f;
    #pragma unroll
    for (int i = 0; i < 4; i++) { float dd = y[i] - mu; s2 += dd * dd; }
    s2 = blockReduceSum(s2);
    float inv = rsqrtf(s2 * (1.f / (float)D_) + LN_EPS);
    #pragma unroll
    for (int i = 0; i < 4; i++) {
        int d = tid + i * 256;
        outp[(long long)tok * D_ + d] = (y[i] - mu) * inv * gam[d] + bet[d];
    }
}

// ---------------- launch ----------------
extern "C" void kernel_launch(void* const* d_in, const int* in_sizes, int n_in,
                              void* d_out, int out_size) {
    const float* emb   = (const float*)d_in[0];
    const float* Wq    = (const float*)d_in[1];
    const float* Wk    = (const float*)d_in[2];
    const float* Wv    = (const float*)d_in[3];
    const float* bsc   = (const float*)d_in[4];
    const float* Wo_w  = (const float*)d_in[5];
    const float* Wo_b  = (const float*)d_in[6];
    const float* ln_g  = (const float*)d_in[7];
    const float* ln_b  = (const float*)d_in[8];
    float* out = (float*)d_out;

    float *pS, *pWo;
    __nv_bfloat16 *pWs, *pQs, *pKs, *pVts, *pEs, *pWqs, *pWks, *pWvs, *pWos, *pCs;
    cudaGetSymbolAddress((void**)&pS,   g_S);
    cudaGetSymbolAddress((void**)&pWs,  g_Ws);
    cudaGetSymbolAddress((void**)&pQs,  g_Qs);
    cudaGetSymbolAddress((void**)&pKs,  g_Ks);
    cudaGetSymbolAddress((void**)&pVts, g_Vts);
    cudaGetSymbolAddress((void**)&pEs,  g_embs);
    cudaGetSymbolAddress((void**)&pWqs, g_Wqs);
    cudaGetSymbolAddress((void**)&pWks, g_Wks);
    cudaGetSymbolAddress((void**)&pWvs, g_Wvs);
    cudaGetSymbolAddress((void**)&pWos, g_Wos);
    cudaGetSymbolAddress((void**)&pCs,  g_Cs);
    cudaGetSymbolAddress((void**)&pWo,  g_wo);

    const long long SD  = (long long)S_ * D_;
    const long long SH  = (long long)S_ * HD_;
    const long long SS  = (long long)S_ * S_;
    const long long EP  = (long long)B_ * SD;          // emb plane
    const long long QP  = (long long)B_ * H_ * SH;     // Q/K/Vt plane
    const long long WP  = (long long)B_ * H_ * SS;     // weights plane
    const long long WQP = (long long)H_ * HD_ * HD_;
    const long long WOP = (long long)D_ * D_;

    const int DSMEM = 131072;   // 2 x 64KB stages
    cudaFuncSetAttribute(mma_gemm, cudaFuncAttributeMaxDynamicSharedMemorySize, DSMEM);

    dim3 blk(256);

    // conversions to split bf16
    split_kernel<<<(unsigned)(EP / 4 / 256), blk>>>(emb, pEs, EP, EP);
    split_kernel<<<(unsigned)(WQP / 4 / 256), blk>>>(Wq, pWqs, WQP, WQP);
    split_kernel<<<(unsigned)(WQP / 4 / 256), blk>>>(Wk, pWks, WQP, WQP);
    split_kernel<<<(unsigned)(WQP / 4 / 256), blk>>>(Wv, pWvs, WQP, WQP);
    split_kernel<<<(unsigned)(WOP / 4 / 256), blk>>>(Wo_w, pWos, WOP, WOP);

    // Q = X @ Wq^T  -> split planes, row-major [b,h,s,e]  (3-term)
    mma_gemm<<<dim3(2, 16, 16), blk, DSMEM>>>(pEs, EP, D_, SD, HD_,
        pWqs, WQP, HD_, 0, (long long)HD_ * HD_,
        pS /*unused*/, pQs, QP, (long long)H_ * SH, SH, HD_, 1, HD_, 1.0f, H_, 1, 1);
    // K  (3-term)
    mma_gemm<<<dim3(2, 16, 16), blk, DSMEM>>>(pEs, EP, D_, SD, HD_,
        pWks, WQP, HD_, 0, (long long)HD_ * HD_,
        pS, pKs, QP, (long long)H_ * SH, SH, HD_, 1, HD_, 1.0f, H_, 1, 1);
    // V, stored transposed [b,h,e,t]  (2-term: drop emb_lo * Wv_hi)
    mma_gemm<<<dim3(2, 16, 16), blk, DSMEM>>>(pEs, EP, D_, SD, HD_,
        pWvs, WQP, HD_, 0, (long long)HD_ * HD_,
        pS, pVts, QP, (long long)H_ * HD_ * S_, (long long)HD_ * S_, 1, S_, HD_, 1.0f, H_, 1, 0);

    // mag1 / v3 / intent mean
    mag_kernel<<<B_ * S_, blk>>>(emb);
    mean_kernel<<<1, blk>>>();

    // scores = (Q @ K^T) / 16 -> fp32 g_S  (3-term)
    mma_gemm<<<dim3(16, 16, 16), blk, DSMEM>>>(pQs, QP, HD_, (long long)H_ * SH, SH,
        pKs, QP, HD_, (long long)H_ * SH, SH,
        pS, pQs /*unused*/, 0, (long long)H_ * SS, SS, S_, 1, HD_, 0.0625f, H_, 0, 1);

    // + biases, softmax -> split bf16 weights
    softmax_kernel<<<dim3(S_, H_, B_), blk>>>(bsc);

    // average weights + guilt -> output regions 1 & 2
    avg_kernel<<<(unsigned)((long long)B_ * SS / 8 / 256), blk>>>(out + EP);
    guilt_kernel<<<(B_ * S_ + 255) / 256, blk>>>(out + EP + (long long)B_ * SS);

    // attended = W @ V -> concat bf16 hi only  (2-term: Whi*Vhi + Whi*Vlo)
    mma_gemm<<<dim3(2, 16, 16), blk, DSMEM>>>(pWs, WP, S_, (long long)H_ * SS, SS,
        pVts, QP, S_, (long long)H_ * HD_ * S_, (long long)HD_ * S_,
        pS, pCs, 0, SD, HD_, D_, 1, S_, 1.0f, H_, 2, 0);

    // out_pre = concat @ Wo^T -> fp32 g_wo  (2-term: Chi*Wohi + Chi*Wolo)
    mma_gemm<<<dim3(8, 64, 1), blk, DSMEM>>>(pCs, 0, D_, 0, 0,
        pWos, WOP, D_, 0, 0,
        pWo, pCs /*unused*/, 0, 0, 0, D_, 1, D_, 1.0f, 1, 0, 0);

    // + Wo_b + residual + LayerNorm -> output region 0
    ln_kernel<<<B_ * S_, blk>>>(emb, Wo_b, ln_g, ln_b, out);
}

// round 10
// speedup vs baseline: 4.9492x; 2.1854x over previous
#include <cuda_runtime.h>
#include <cuda_fp16.h>
#include <math.h>

#define B_  4
#define S_  2048
#define D_  1024
#define H_  4
#define HD_ 256
#define LN_EPS 1e-5f

typedef unsigned int       u32;
typedef unsigned long long u64;

// ---------------- device scratch (no cudaMalloc allowed) ----------------
__device__ __align__(16) float  g_S [(size_t)B_*H_*S_*S_];     // fp32 scores
__device__ __align__(16) __half g_W [(size_t)B_*H_*S_*S_];     // softmax weights fp16
__device__ __align__(16) __half g_Q [(size_t)B_*H_*S_*HD_];
__device__ __align__(16) __half g_K [(size_t)B_*H_*S_*HD_];
__device__ __align__(16) __half g_Vt[(size_t)B_*H_*HD_*S_];    // V transposed [b,h,e,t]
__device__ __align__(16) __half g_E [(size_t)B_*S_*D_];        // emb fp16
__device__ __align__(16) __half g_Wq[(size_t)H_*HD_*HD_];
__device__ __align__(16) __half g_Wk[(size_t)H_*HD_*HD_];
__device__ __align__(16) __half g_Wv[(size_t)H_*HD_*HD_];
__device__ __align__(16) __half g_Wo[(size_t)D_*D_];
__device__ __align__(16) __half g_C [(size_t)B_*S_*D_];        // concat fp16
__device__ __align__(16) float  g_wo[(size_t)B_*S_*D_];        // Wo output pre-LN
__device__ float g_mag1[B_*S_];
__device__ float g_v3[B_*S_];
__device__ float g_mean;

// ---------------- helpers ----------------
__device__ __forceinline__ u32 smem_to_u32(const void* p) {
    u32 a;
    asm("{ .reg .u64 t; cvta.to.shared.u64 t, %1; cvt.u32.u64 %0, t; }" : "=r"(a) : "l"(p));
    return a;
}
static __device__ __forceinline__ u32 swz(u32 o) { return o ^ ((o >> 3) & 0x70u); }

__device__ __forceinline__ void cp_async16(u32 dst, const void* src) {
    asm volatile("cp.async.cg.shared.global [%0], [%1], 16;" :: "r"(dst), "l"(src));
}
#define CP_COMMIT()  asm volatile("cp.async.commit_group;" ::: "memory")
#define CP_WAIT(N)   asm volatile("cp.async.wait_group %0;" :: "n"(N) : "memory")

__device__ __forceinline__ void ldsm4(u32 addr, u32& r0, u32& r1, u32& r2, u32& r3) {
    asm volatile("ldmatrix.sync.aligned.m8n8.x4.shared.b16 {%0,%1,%2,%3}, [%4];"
        : "=r"(r0), "=r"(r1), "=r"(r2), "=r"(r3) : "r"(addr));
}
__device__ __forceinline__ void mma16816(float* c, const u32* a, u32 b0, u32 b1) {
    asm volatile("mma.sync.aligned.m16n8k16.row.col.f32.f16.f16.f32 "
        "{%0,%1,%2,%3}, {%4,%5,%6,%7}, {%8,%9}, {%0,%1,%2,%3};"
        : "+f"(c[0]), "+f"(c[1]), "+f"(c[2]), "+f"(c[3])
        : "r"(a[0]), "r"(a[1]), "r"(a[2]), "r"(a[3]), "r"(b0), "r"(b1));
}

// ============================================================================
// Batched NT GEMM via fp16 mma.sync: C = alpha * (A @ B^T).
// A: [M,K] rows K-major, row stride lda. B: [N,K] rows K-major, row stride ldb.
// CTA tile 128x128, K-chunk 64, 3-stage cp.async pipeline (3 x 32KB smem).
// Stage layout: A @0, B @16K (each 128 rows x 128B, SW128 swizzle).
// Output: outHalf ? fp16 Ch : fp32 Cf; element (m,n) at m*Crs + n*Ccs.
// Requires K multiple of 64, nc = K/64 >= 3.
// ============================================================================
__device__ __forceinline__ void stage_load(u32 sbase, int buf,
    const __half* A, int lda, int m0,
    const __half* Bm, int ldb, int n0,
    long long kof, int tid)
{
    #pragma unroll
    for (int it = 0; it < 8; it++) {
        int idx = tid + it * 256;
        int tile = idx >> 10;                // 0 A, 1 B
        int rem = idx & 1023;
        int r = rem >> 3, c = rem & 7;
        const __half* src = (tile == 0)
            ? A  + (long long)(m0 + r) * lda + kof + c * 8
            : Bm + (long long)(n0 + r) * ldb + kof + c * 8;
        u32 dst = sbase + (u32)buf * 32768u + (u32)tile * 16384u + swz((u32)(r * 128 + c * 16));
        cp_async16(dst, src);
    }
    CP_COMMIT();
}

__global__ void __launch_bounds__(256, 2)
mma_gemm(const __half* __restrict__ A, int lda, long long Asb, long long Ash,
         const __half* __restrict__ Bm, int ldb, long long Bsb, long long Bsh,
         float* __restrict__ Cf, __half* __restrict__ Ch,
         long long Csb, long long Csh, long long Crs, long long Ccs,
         int K, float alpha, int Hdiv, int outHalf)
{
    extern __shared__ __align__(16) char smem[];
    const u32 sbase = smem_to_u32(smem);

    int tid = threadIdx.x, lane = tid & 31, wid = tid >> 5;
    int wm = wid & 3, wn = wid >> 2;                 // warp tile 32x64 at (wm*32, wn*64)
    int z = blockIdx.z, b = z / Hdiv, h = z % Hdiv;
    A  += b * Asb + h * Ash;
    Bm += b * Bsb + h * Bsh;
    const long long Cb = b * Csb + h * Csh;

    const int m0 = blockIdx.y * 128, n0 = blockIdx.x * 128;

    const int ph_row  = (lane & 7) + ((lane >> 3) & 1) * 8;
    const int ph_byte = (lane >> 4) * 16;

    float acc[2][8][4];
    #pragma unroll
    for (int i = 0; i < 2; i++)
        #pragma unroll
        for (int j = 0; j < 8; j++)
            #pragma unroll
            for (int k = 0; k < 4; k++) acc[i][j][k] = 0.f;

    const int nc = K >> 6;                           // >= 3 for all our shapes
    stage_load(sbase, 0, A, lda, m0, Bm, ldb, n0, 0,   tid);
    stage_load(sbase, 1, A, lda, m0, Bm, ldb, n0, 64,  tid);
    stage_load(sbase, 2, A, lda, m0, Bm, ldb, n0, 128, tid);

    int buf = 0;
    for (int ci = 0; ci < nc; ci++) {
        CP_WAIT(2);
        __syncthreads();

        u32 sb = sbase + (u32)buf * 32768u;
        #pragma unroll
        for (int ks = 0; ks < 4; ks++) {
            u32 afr[2][4];
            #pragma unroll
            for (int mh = 0; mh < 2; mh++) {
                int row = wm * 32 + mh * 16 + ph_row;
                u32 ad = sb + swz((u32)(row * 128 + ks * 32 + ph_byte));
                ldsm4(ad, afr[mh][0], afr[mh][1], afr[mh][2], afr[mh][3]);
            }
            u32 bfr[4][4];
            #pragma unroll
            for (int nq = 0; nq < 4; nq++) {
                int row = wn * 64 + nq * 16 + ph_row;
                u32 ad = sb + 16384u + swz((u32)(row * 128 + ks * 32 + ph_byte));
                ldsm4(ad, bfr[nq][0], bfr[nq][1], bfr[nq][2], bfr[nq][3]);
            }
            #pragma unroll
            for (int mh = 0; mh < 2; mh++)
                #pragma unroll
                for (int nq = 0; nq < 4; nq++) {
                    mma16816(acc[mh][nq * 2 + 0], afr[mh], bfr[nq][0], bfr[nq][2]);
                    mma16816(acc[mh][nq * 2 + 1], afr[mh], bfr[nq][1], bfr[nq][3]);
                }
        }
        __syncthreads();
        if (ci + 3 < nc)
            stage_load(sbase, buf, A, lda, m0, Bm, ldb, n0, (long long)(ci + 3) * 64, tid);
        else
            CP_COMMIT();                             // empty group keeps wait count aligned
        buf = (buf == 2) ? 0 : buf + 1;
    }

    // epilogue: d-frag lane map: rows lane>>2 (+8), cols (lane&3)*2 (+1)
    #pragma unroll
    for (int mh = 0; mh < 2; mh++)
        #pragma unroll
        for (int nf = 0; nf < 8; nf++) {
            float* c = acc[mh][nf];
            long long mA = m0 + wm * 32 + mh * 16 + (lane >> 2);
            long long nA = n0 + wn * 64 + nf * 8 + (lane & 3) * 2;
            if (Ccs == 1) {
                #pragma unroll
                for (int qr = 0; qr < 2; qr++) {     // two rows, n/n+1 contiguous
                    long long m = mA + qr * 8;
                    long long co = Cb + m * Crs + nA;
                    float v0 = alpha * c[qr * 2 + 0], v1 = alpha * c[qr * 2 + 1];
                    if (outHalf) *(__half2*)(Ch + co) = __floats2half2_rn(v0, v1);
                    else         *(float2*)(Cf + co) = make_float2(v0, v1);
                }
            } else {                                 // Crs==1 (Vt): scalar stores
                #pragma unroll
                for (int q = 0; q < 4; q++) {
                    long long m = mA + (q >> 1) * 8;
                    long long n = nA + (q & 1);
                    float v = alpha * c[q];
                    long long co = Cb + m + n * Ccs;
                    if (outHalf) Ch[co] = __float2half_rn(v);
                    else         Cf[co] = v;
                }
            }
        }
}

// ---------------- fp32 -> fp16 conversion (8 elems/thread) ----------------
__global__ __launch_bounds__(256) void cvt_kernel(const float* __restrict__ x,
                                                  __half* __restrict__ y) {
    long long i = (long long)blockIdx.x * 256 + threadIdx.x;   // 8-elem groups
    float4 a = ((const float4*)x)[2 * i];
    float4 b = ((const float4*)x)[2 * i + 1];
    __half2 h0 = __floats2half2_rn(a.x, a.y);
    __half2 h1 = __floats2half2_rn(a.z, a.w);
    __half2 h2 = __floats2half2_rn(b.x, b.y);
    __half2 h3 = __floats2half2_rn(b.z, b.w);
    uint4 o;
    o.x = *(u32*)&h0; o.y = *(u32*)&h1; o.z = *(u32*)&h2; o.w = *(u32*)&h3;
    ((uint4*)y)[i] = o;
}

// ---------------- block reductions ----------------
__device__ __forceinline__ float blockReduceSum(float v) {
    __shared__ float sh[33];
    __syncthreads();
    #pragma unroll
    for (int o = 16; o; o >>= 1) v += __shfl_xor_sync(0xffffffffu, v, o);
    if ((threadIdx.x & 31) == 0) sh[threadIdx.x >> 5] = v;
    __syncthreads();
    if (threadIdx.x < 32) {
        v = (threadIdx.x < (blockDim.x >> 5)) ? sh[threadIdx.x] : 0.f;
        #pragma unroll
        for (int o = 16; o; o >>= 1) v += __shfl_xor_sync(0xffffffffu, v, o);
        if (threadIdx.x == 0) sh[32] = v;
    }
    __syncthreads();
    return sh[32];
}
__device__ __forceinline__ float blockReduceMax(float v) {
    __shared__ float sh[33];
    __syncthreads();
    #pragma unroll
    for (int o = 16; o; o >>= 1) v = fmaxf(v, __shfl_xor_sync(0xffffffffu, v, o));
    if ((threadIdx.x & 31) == 0) sh[threadIdx.x >> 5] = v;
    __syncthreads();
    if (threadIdx.x < 32) {
        v = (threadIdx.x < (blockDim.x >> 5)) ? sh[threadIdx.x] : -INFINITY;
        #pragma unroll
        for (int o = 16; o; o >>= 1) v = fmaxf(v, __shfl_xor_sync(0xffffffffu, v, o));
        if (threadIdx.x == 0) sh[32] = v;
    }
    __syncthreads();
    return sh[32];
}

// ---------------- mag1 / v3 ----------------
__global__ __launch_bounds__(256) void mag_kernel(const float* __restrict__ emb) {
    int row = blockIdx.x;
    int tid = threadIdx.x;
    float v = emb[(long long)row * D_ + HD_ + tid];
    float ss = blockReduceSum(v * v);
    if (tid == 0) {
        g_mag1[row] = sqrtf(ss);
        g_v3[row]   = emb[(long long)row * D_ + (D_ - 1)];
    }
}
__global__ __launch_bounds__(256) void mean_kernel() {
    int tid = threadIdx.x;
    float acc = 0.f;
    for (int b = 0; b < B_; b++) {
        float v = 0.f;
        for (int i = tid; i < S_; i += 256) v += g_mag1[b * S_ + i];
        v = blockReduceSum(v);
        acc += v * v;
    }
    if (tid == 0) g_mean = acc / ((float)B_ * (float)S_ * (float)S_);
}

// ---------------- bias + softmax: g_S -> fp16 weights ----------------
__global__ __launch_bounds__(256) void softmax_kernel(const float* __restrict__ bias_scalars) {
    int s = blockIdx.x, h = blockIdx.y, b = blockIdx.z;
    int tid = threadIdx.x;
    const long long roff = (((long long)(b * H_ + h)) * S_ + s) * S_;
    const float4* row4 = (const float4*)(g_S + roff);
    __half2* w2 = (__half2*)(g_W + roff);
    float bs = bias_scalars[h];
    float mean = g_mean;
    float ms = g_mag1[b * S_ + s];
    float vs = g_v3[b * S_ + s];

    float vals[8];
    #pragma unroll
    for (int i = 0; i < 2; i++) {
        int j = tid + i * 256;
        float4 x = row4[j];
        int t0 = 4 * j;
        float* vv = vals + i * 4;
        vv[0] = x.x; vv[1] = x.y; vv[2] = x.z; vv[3] = x.w;
        #pragma unroll
        for (int q = 0; q < 4; q++) {
            int t = t0 + q;
            float bias;
            if (h == 0)      bias = (t > s) ? bs : 0.f;
            else if (h == 1) bias = (ms * g_mag1[b * S_ + t] > mean) ? bs : 0.f;
            else if (h == 2) bias = expf(fabsf((float)(t - s)) * (-1.f / (float)S_)) * bs;
            else             bias = (vs * g_v3[b * S_ + t] > 0.5f) ? bs : 0.f;
            vv[q] += bias;
        }
    }
    float m = -INFINITY;
    #pragma unroll
    for (int i = 0; i < 8; i++) m = fmaxf(m, vals[i]);
    m = blockReduceMax(m);
    float sum = 0.f;
    #pragma unroll
    for (int i = 0; i < 8; i++) { vals[i] = expf(vals[i] - m); sum += vals[i]; }
    sum = blockReduceSum(sum);
    float inv = 1.f / sum;
    #pragma unroll
    for (int i = 0; i < 2; i++) {
        int j = tid + i * 256;
        w2[2 * j]     = __floats2half2_rn(vals[i * 4 + 0] * inv, vals[i * 4 + 1] * inv);
        w2[2 * j + 1] = __floats2half2_rn(vals[i * 4 + 2] * inv, vals[i * 4 + 3] * inv);
    }
}

// ---------------- head-average of fp16 weights -> output region 1 ----------------
__global__ __launch_bounds__(256) void avg_kernel(float* __restrict__ outAvg) {
    long long idx = (long long)blockIdx.x * 256 + threadIdx.x;   // 8-element groups
    const long long bq = (long long)S_ * S_ / 8;
    int b = (int)(idx / bq);
    long long r = idx - (long long)b * bq;
    const uint4* w = (const uint4*)g_W;
    float acc[8];
    #pragma unroll
    for (int q = 0; q < 8; q++) acc[q] = 0.f;
    #pragma unroll
    for (int h = 0; h < H_; h++) {
        uint4 a = w[((long long)(b * H_ + h)) * bq + r];
        const u32 ar[4] = {a.x, a.y, a.z, a.w};
        #pragma unroll
        for (int p = 0; p < 4; p++) {
            float2 f = __half22float2(*(const __half2*)&ar[p]);
            acc[2 * p]     += f.x;
            acc[2 * p + 1] += f.y;
        }
    }
    ((float4*)outAvg)[2 * idx]     = make_float4(0.25f * acc[0], 0.25f * acc[1],
                                                 0.25f * acc[2], 0.25f * acc[3]);
    ((float4*)outAvg)[2 * idx + 1] = make_float4(0.25f * acc[4], 0.25f * acc[5],
                                                 0.25f * acc[6], 0.25f * acc[7]);
}

__global__ void guilt_kernel(float* __restrict__ outG) {
    int i = blockIdx.x * 256 + threadIdx.x;
    if (i < B_ * S_) outG[i] = 1.0f / (float)S_;
}

// ---------------- bias + residual + LayerNorm ----------------
__global__ __launch_bounds__(256) void ln_kernel(const float* __restrict__ emb,
                                                 const float* __restrict__ Wo_b,
                                                 const float* __restrict__ gam,
                                                 const float* __restrict__ bet,
                                                 float* __restrict__ outp) {
    int tok = blockIdx.x;
    int tid = threadIdx.x;
    float y[4];
    float s1 = 0.f;
    #pragma unroll
    for (int i = 0; i < 4; i++) {
        int d = tid + i * 256;
        y[i] = g_wo[(long long)tok * D_ + d] + Wo_b[d] + emb[(long long)tok * D_ + d];
        s1 += y[i];
    }
    s1 = blockReduceSum(s1);
    float mu = s1 * (1.f / (float)D_);
    float s2 = 0.f;
    #pragma unroll
    for (int i = 0; i < 4; i++) { float dd = y[i] - mu; s2 += dd * dd; }
    s2 = blockReduceSum(s2);
    float inv = rsqrtf(s2 * (1.f / (float)D_) + LN_EPS);
    #pragma unroll
    for (int i = 0; i < 4; i++) {
        int d = tid + i * 256;
        outp[(long long)tok * D_ + d] = (y[i] - mu) * inv * gam[d] + bet[d];
    }
}

// ---------------- launch ----------------
extern "C" void kernel_launch(void* const* d_in, const int* in_sizes, int n_in,
                              void* d_out, int out_size) {
    const float* emb   = (const float*)d_in[0];
    const float* Wq    = (const float*)d_in[1];
    const float* Wk    = (const float*)d_in[2];
    const float* Wv    = (const float*)d_in[3];
    const float* bsc   = (const float*)d_in[4];
    const float* Wo_w  = (const float*)d_in[5];
    const float* Wo_b  = (const float*)d_in[6];
    const float* ln_g  = (const float*)d_in[7];
    const float* ln_b  = (const float*)d_in[8];
    float* out = (float*)d_out;

    float *pS, *pWoO;
    __half *pW, *pQ, *pK, *pVt, *pE, *pWq, *pWk, *pWv, *pWo, *pC;
    cudaGetSymbolAddress((void**)&pS,   g_S);
    cudaGetSymbolAddress((void**)&pW,   g_W);
    cudaGetSymbolAddress((void**)&pQ,   g_Q);
    cudaGetSymbolAddress((void**)&pK,   g_K);
    cudaGetSymbolAddress((void**)&pVt,  g_Vt);
    cudaGetSymbolAddress((void**)&pE,   g_E);
    cudaGetSymbolAddress((void**)&pWq,  g_Wq);
    cudaGetSymbolAddress((void**)&pWk,  g_Wk);
    cudaGetSymbolAddress((void**)&pWv,  g_Wv);
    cudaGetSymbolAddress((void**)&pWo,  g_Wo);
    cudaGetSymbolAddress((void**)&pC,   g_C);
    cudaGetSymbolAddress((void**)&pWoO, g_wo);

    const long long SD  = (long long)S_ * D_;
    const long long SH  = (long long)S_ * HD_;
    const long long SS  = (long long)S_ * S_;
    const long long EP  = (long long)B_ * SD;
    const long long WQP = (long long)H_ * HD_ * HD_;
    const long long WOP = (long long)D_ * D_;

    const int DSMEM = 3 * 32768;   // 3-stage pipeline, 96KB
    cudaFuncSetAttribute(mma_gemm, cudaFuncAttributeMaxDynamicSharedMemorySize, DSMEM);

    dim3 blk(256);

    // fp32 -> fp16 conversions
    cvt_kernel<<<(unsigned)(EP / 8 / 256), blk>>>(emb, pE);
    cvt_kernel<<<(unsigned)(WQP / 8 / 256), blk>>>(Wq, pWq);
    cvt_kernel<<<(unsigned)(WQP / 8 / 256), blk>>>(Wk, pWk);
    cvt_kernel<<<(unsigned)(WQP / 8 / 256), blk>>>(Wv, pWv);
    cvt_kernel<<<(unsigned)(WOP / 8 / 256), blk>>>(Wo_w, pWo);

    // Q = X @ Wq^T -> fp16 [b,h,s,e]
    mma_gemm<<<dim3(2, 16, 16), blk, DSMEM>>>(pE, D_, SD, HD_,
        pWq, HD_, 0, (long long)HD_ * HD_,
        pS /*unused*/, pQ, (long long)H_ * SH, SH, HD_, 1, HD_, 1.0f, H_, 1);
    // K
    mma_gemm<<<dim3(2, 16, 16), blk, DSMEM>>>(pE, D_, SD, HD_,
        pWk, HD_, 0, (long long)HD_ * HD_,
        pS, pK, (long long)H_ * SH, SH, HD_, 1, HD_, 1.0f, H_, 1);
    // V, stored transposed [b,h,e,t]
    mma_gemm<<<dim3(2, 16, 16), blk, DSMEM>>>(pE, D_, SD, HD_,
        pWv, HD_, 0, (long long)HD_ * HD_,
        pS, pVt, (long long)H_ * HD_ * S_, (long long)HD_ * S_, 1, S_, HD_, 1.0f, H_, 1);

    // mag1 / v3 / intent mean
    mag_kernel<<<B_ * S_, blk>>>(emb);
    mean_kernel<<<1, blk>>>();

    // scores = (Q @ K^T) / 16 -> fp32 g_S
    mma_gemm<<<dim3(16, 16, 16), blk, DSMEM>>>(pQ, HD_, (long long)H_ * SH, SH,
        pK, HD_, (long long)H_ * SH, SH,
        pS, pW /*unused*/, (long long)H_ * SS, SS, S_, 1, HD_, 0.0625f, H_, 0);

    // + biases, softmax -> fp16 weights
    softmax_kernel<<<dim3(S_, H_, B_), blk>>>(bsc);

    // average weights + guilt -> output regions 1 & 2
    avg_kernel<<<(unsigned)((long long)B_ * SS / 8 / 256), blk>>>(out + EP);
    guilt_kernel<<<(B_ * S_ + 255) / 256, blk>>>(out + EP + (long long)B_ * SS);

    // attended = W @ V -> concat fp16 [b,s,h*hd+e]
    mma_gemm<<<dim3(2, 16, 16), blk, DSMEM>>>(pW, S_, (long long)H_ * SS, SS,
        pVt, S_, (long long)H_ * HD_ * S_, (long long)HD_ * S_,
        pS, pC, SD, HD_, D_, 1, S_, 1.0f, H_, 1);

    // out_pre = concat @ Wo^T -> fp32 g_wo
    mma_gemm<<<dim3(8, 64, 1), blk, DSMEM>>>(pC, D_, 0, 0,
        pWo, D_, 0, 0,
        pWoO, pC /*unused*/, 0, 0, D_, 1, D_, 1.0f, 1, 0);

    // + Wo_b + residual + LayerNorm -> output region 0
    ln_kernel<<<B_ * S_, blk>>>(emb, Wo_b, ln_g, ln_b, out);
}

// round 11
// speedup vs baseline: 5.0095x; 1.0122x over previous
#include <cuda_runtime.h>
#include <cuda_fp16.h>
#include <math.h>

#define B_  4
#define S_  2048
#define D_  1024
#define H_  4
#define HD_ 256
#define LN_EPS 1e-5f

typedef unsigned int       u32;
typedef unsigned long long u64;

// ---------------- device scratch (no cudaMalloc allowed) ----------------
__device__ __align__(16) float  g_S [(size_t)B_*H_*S_*S_];     // fp32 scores
__device__ __align__(16) __half g_W [(size_t)B_*H_*S_*S_];     // softmax weights fp16
__device__ __align__(16) __half g_Q [(size_t)B_*H_*S_*HD_];
__device__ __align__(16) __half g_K [(size_t)B_*H_*S_*HD_];
__device__ __align__(16) __half g_Vt[(size_t)B_*H_*HD_*S_];    // V transposed [b,h,e,t]
__device__ __align__(16) __half g_E [(size_t)B_*S_*D_];        // emb fp16
__device__ __align__(16) __half g_Wq[(size_t)H_*HD_*HD_];
__device__ __align__(16) __half g_Wk[(size_t)H_*HD_*HD_];
__device__ __align__(16) __half g_Wv[(size_t)H_*HD_*HD_];
__device__ __align__(16) __half g_Wo[(size_t)D_*D_];
__device__ __align__(16) __half g_C [(size_t)B_*S_*D_];        // concat fp16
__device__ __align__(16) float  g_wo[(size_t)B_*S_*D_];        // Wo output pre-LN
__device__ float g_mag1[B_*S_];
__device__ float g_v3[B_*S_];
__device__ float g_mean;

// ---------------- helpers ----------------
__device__ __forceinline__ u32 smem_to_u32(const void* p) {
    u32 a;
    asm("{ .reg .u64 t; cvta.to.shared.u64 t, %1; cvt.u32.u64 %0, t; }" : "=r"(a) : "l"(p));
    return a;
}
static __device__ __forceinline__ u32 swz(u32 o) { return o ^ ((o >> 3) & 0x70u); }

__device__ __forceinline__ void cp_async16(u32 dst, const void* src) {
    asm volatile("cp.async.cg.shared.global [%0], [%1], 16;" :: "r"(dst), "l"(src));
}
#define CP_COMMIT()  asm volatile("cp.async.commit_group;" ::: "memory")
#define CP_WAIT(N)   asm volatile("cp.async.wait_group %0;" :: "n"(N) : "memory")

__device__ __forceinline__ void ldsm4(u32 addr, u32& r0, u32& r1, u32& r2, u32& r3) {
    asm volatile("ldmatrix.sync.aligned.m8n8.x4.shared.b16 {%0,%1,%2,%3}, [%4];"
        : "=r"(r0), "=r"(r1), "=r"(r2), "=r"(r3) : "r"(addr));
}
__device__ __forceinline__ void mma16816(float* c, const u32* a, u32 b0, u32 b1) {
    asm volatile("mma.sync.aligned.m16n8k16.row.col.f32.f16.f16.f32 "
        "{%0,%1,%2,%3}, {%4,%5,%6,%7}, {%8,%9}, {%0,%1,%2,%3};"
        : "+f"(c[0]), "+f"(c[1]), "+f"(c[2]), "+f"(c[3])
        : "r"(a[0]), "r"(a[1]), "r"(a[2]), "r"(a[3]), "r"(b0), "r"(b1));
}

// ============================================================================
// Batched NT GEMM via fp16 mma.sync: C = alpha * (A @ B^T).
// A: [M,K] rows K-major, stride lda. B: [N,K] rows K-major, stride ldb.
// CTA tile 128x256, K-chunk 64, 3-stage cp.async pipeline (3 x 48KB smem).
// Stage layout: A @0 (16KB), B @16K (32KB); 128B rows, SW128 swizzle.
// 8 warps: wm=wid&3 (4 x 32 rows), wn=wid>>2 (2 x 128 cols). Warp tile 32x128.
// Output: outHalf ? fp16 Ch : fp32 Cf; element (m,n) at m*Crs + n*Ccs.
// Requires M%128==0, N%256==0, K%64==0, K/64 >= 3.
// ============================================================================
#define STG_SZ 49152u

__device__ __forceinline__ void stage_load(u32 sbase, int buf,
    const __half* A, int lda, int m0,
    const __half* Bm, int ldb, int n0,
    long long kof, int tid)
{
    #pragma unroll
    for (int it = 0; it < 12; it++) {
        int idx = tid + it * 256;                    // 0..3071
        const __half* src;
        u32 dst;
        if (idx < 1024) {                            // A: 128 rows x 8 chunks
            int r = idx >> 3, c = idx & 7;
            src = A + (long long)(m0 + r) * lda + kof + c * 8;
            dst = sbase + (u32)buf * STG_SZ + swz((u32)(r * 128 + c * 16));
        } else {                                     // B: 256 rows x 8 chunks
            int j = idx - 1024;
            int r = j >> 3, c = j & 7;
            src = Bm + (long long)(n0 + r) * ldb + kof + c * 8;
            dst = sbase + (u32)buf * STG_SZ + 16384u + swz((u32)(r * 128 + c * 16));
        }
        cp_async16(dst, src);
    }
    CP_COMMIT();
}

__global__ void __launch_bounds__(256, 1)
mma_gemm(const __half* __restrict__ A, int lda, long long Asb, long long Ash,
         const __half* __restrict__ Bm, int ldb, long long Bsb, long long Bsh,
         float* __restrict__ Cf, __half* __restrict__ Ch,
         long long Csb, long long Csh, long long Crs, long long Ccs,
         int K, float alpha, int Hdiv, int outHalf)
{
    extern __shared__ __align__(16) char smem[];
    const u32 sbase = smem_to_u32(smem);

    int tid = threadIdx.x, lane = tid & 31, wid = tid >> 5;
    int wm = wid & 3, wn = wid >> 2;                 // warp tile 32x128
    int z = blockIdx.z, b = z / Hdiv, h = z % Hdiv;
    A  += b * Asb + h * Ash;
    Bm += b * Bsb + h * Bsh;
    const long long Cb = b * Csb + h * Csh;

    const int m0 = blockIdx.y * 128, n0 = blockIdx.x * 256;

    const int ph_row  = (lane & 7) + ((lane >> 3) & 1) * 8;
    const int ph_byte = (lane >> 4) * 16;

    float acc[2][16][4];
    #pragma unroll
    for (int i = 0; i < 2; i++)
        #pragma unroll
        for (int j = 0; j < 16; j++)
            #pragma unroll
            for (int k = 0; k < 4; k++) acc[i][j][k] = 0.f;

    const int nc = K >> 6;
    stage_load(sbase, 0, A, lda, m0, Bm, ldb, n0, 0,   tid);
    stage_load(sbase, 1, A, lda, m0, Bm, ldb, n0, 64,  tid);
    stage_load(sbase, 2, A, lda, m0, Bm, ldb, n0, 128, tid);

    int buf = 0;
    for (int ci = 0; ci < nc; ci++) {
        CP_WAIT(2);
        __syncthreads();

        u32 sb = sbase + (u32)buf * STG_SZ;
        #pragma unroll
        for (int ks = 0; ks < 4; ks++) {
            u32 afr[2][4];
            #pragma unroll
            for (int mh = 0; mh < 2; mh++) {
                int row = wm * 32 + mh * 16 + ph_row;
                u32 ad = sb + swz((u32)(row * 128 + ks * 32 + ph_byte));
                ldsm4(ad, afr[mh][0], afr[mh][1], afr[mh][2], afr[mh][3]);
            }
            u32 bfr[8][4];
            #pragma unroll
            for (int nq = 0; nq < 8; nq++) {
                int row = wn * 128 + nq * 16 + ph_row;
                u32 ad = sb + 16384u + swz((u32)(row * 128 + ks * 32 + ph_byte));
                ldsm4(ad, bfr[nq][0], bfr[nq][1], bfr[nq][2], bfr[nq][3]);
            }
            #pragma unroll
            for (int mh = 0; mh < 2; mh++)
                #pragma unroll
                for (int nq = 0; nq < 8; nq++) {
                    mma16816(acc[mh][nq * 2 + 0], afr[mh], bfr[nq][0], bfr[nq][2]);
                    mma16816(acc[mh][nq * 2 + 1], afr[mh], bfr[nq][1], bfr[nq][3]);
                }
        }
        __syncthreads();
        if (ci + 3 < nc)
            stage_load(sbase, buf, A, lda, m0, Bm, ldb, n0, (long long)(ci + 3) * 64, tid);
        else
            CP_COMMIT();                             // keep wait count aligned
        buf = (buf == 2) ? 0 : buf + 1;
    }

    // epilogue: d-frag lane map: rows lane>>2 (+8), cols (lane&3)*2 (+1)
    #pragma unroll
    for (int mh = 0; mh < 2; mh++)
        #pragma unroll
        for (int nf = 0; nf < 16; nf++) {
            float* c = acc[mh][nf];
            long long mA = m0 + wm * 32 + mh * 16 + (lane >> 2);
            long long nA = n0 + wn * 128 + nf * 8 + (lane & 3) * 2;
            if (Ccs == 1) {
                #pragma unroll
                for (int qr = 0; qr < 2; qr++) {
                    long long m = mA + qr * 8;
                    long long co = Cb + m * Crs + nA;
                    float v0 = alpha * c[qr * 2 + 0], v1 = alpha * c[qr * 2 + 1];
                    if (outHalf) *(__half2*)(Ch + co) = __floats2half2_rn(v0, v1);
                    else         *(float2*)(Cf + co) = make_float2(v0, v1);
                }
            } else {                                 // Crs==1 (Vt): scalar stores
                #pragma unroll
                for (int q = 0; q < 4; q++) {
                    long long m = mA + (q >> 1) * 8;
                    long long n = nA + (q & 1);
                    float v = alpha * c[q];
                    long long co = Cb + m + n * Ccs;
                    if (outHalf) Ch[co] = __float2half_rn(v);
                    else         Cf[co] = v;
                }
            }
        }
}

// ---------------- fp32 -> fp16 conversion (8 elems/thread) ----------------
__global__ __launch_bounds__(256) void cvt_kernel(const float* __restrict__ x,
                                                  __half* __restrict__ y) {
    long long i = (long long)blockIdx.x * 256 + threadIdx.x;
    float4 a = ((const float4*)x)[2 * i];
    float4 b = ((const float4*)x)[2 * i + 1];
    __half2 h0 = __floats2half2_rn(a.x, a.y);
    __half2 h1 = __floats2half2_rn(a.z, a.w);
    __half2 h2 = __floats2half2_rn(b.x, b.y);
    __half2 h3 = __floats2half2_rn(b.z, b.w);
    uint4 o;
    o.x = *(u32*)&h0; o.y = *(u32*)&h1; o.z = *(u32*)&h2; o.w = *(u32*)&h3;
    ((uint4*)y)[i] = o;
}

// ---------------- block reductions ----------------
__device__ __forceinline__ float blockReduceSum(float v) {
    __shared__ float sh[33];
    __syncthreads();
    #pragma unroll
    for (int o = 16; o; o >>= 1) v += __shfl_xor_sync(0xffffffffu, v, o);
    if ((threadIdx.x & 31) == 0) sh[threadIdx.x >> 5] = v;
    __syncthreads();
    if (threadIdx.x < 32) {
        v = (threadIdx.x < (blockDim.x >> 5)) ? sh[threadIdx.x] : 0.f;
        #pragma unroll
        for (int o = 16; o; o >>= 1) v += __shfl_xor_sync(0xffffffffu, v, o);
        if (threadIdx.x == 0) sh[32] = v;
    }
    __syncthreads();
    return sh[32];
}
__device__ __forceinline__ float blockReduceMax(float v) {
    __shared__ float sh[33];
    __syncthreads();
    #pragma unroll
    for (int o = 16; o; o >>= 1) v = fmaxf(v, __shfl_xor_sync(0xffffffffu, v, o));
    if ((threadIdx.x & 31) == 0) sh[threadIdx.x >> 5] = v;
    __syncthreads();
    if (threadIdx.x < 32) {
        v = (threadIdx.x < (blockDim.x >> 5)) ? sh[threadIdx.x] : -INFINITY;
        #pragma unroll
        for (int o = 16; o; o >>= 1) v = fmaxf(v, __shfl_xor_sync(0xffffffffu, v, o));
        if (threadIdx.x == 0) sh[32] = v;
    }
    __syncthreads();
    return sh[32];
}

// ---------------- mag1 / v3 ----------------
__global__ __launch_bounds__(256) void mag_kernel(const float* __restrict__ emb) {
    int row = blockIdx.x;
    int tid = threadIdx.x;
    float v = emb[(long long)row * D_ + HD_ + tid];
    float ss = blockReduceSum(v * v);
    if (tid == 0) {
        g_mag1[row] = sqrtf(ss);
        g_v3[row]   = emb[(long long)row * D_ + (D_ - 1)];
    }
}
__global__ __launch_bounds__(256) void mean_kernel() {
    int tid = threadIdx.x;
    float acc = 0.f;
    for (int b = 0; b < B_; b++) {
        float v = 0.f;
        for (int i = tid; i < S_; i += 256) v += g_mag1[b * S_ + i];
        v = blockReduceSum(v);
        acc += v * v;
    }
    if (tid == 0) g_mean = acc / ((float)B_ * (float)S_ * (float)S_);
}

// ---------------- bias + softmax over all 4 heads + head-average ----------------
// One block per (s, b). Writes fp16 weights for each head AND the fp32 head
// average (from pre-rounding fp32 weights) directly to the output region.
__global__ __launch_bounds__(256) void softmax_avg_kernel(const float* __restrict__ bias_scalars,
                                                          float* __restrict__ outAvg) {
    int s = blockIdx.x, b = blockIdx.y;
    int tid = threadIdx.x;
    float mean = g_mean;
    float ms = g_mag1[b * S_ + s];
    float vs = g_v3[b * S_ + s];

    float avg[8];
    #pragma unroll
    for (int q = 0; q < 8; q++) avg[q] = 0.f;

    #pragma unroll
    for (int h = 0; h < H_; h++) {
        const long long roff = (((long long)(b * H_ + h)) * S_ + s) * S_;
        const float4* row4 = (const float4*)(g_S + roff);
        __half2* w2 = (__half2*)(g_W + roff);
        float bs = bias_scalars[h];

        float vals[8];
        #pragma unroll
        for (int i = 0; i < 2; i++) {
            int j = tid + i * 256;
            float4 x = row4[j];
            int t0 = 4 * j;
            float* vv = vals + i * 4;
            vv[0] = x.x; vv[1] = x.y; vv[2] = x.z; vv[3] = x.w;
            #pragma unroll
            for (int q = 0; q < 4; q++) {
                int t = t0 + q;
                float bias;
                if (h == 0)      bias = (t > s) ? bs : 0.f;
                else if (h == 1) bias = (ms * g_mag1[b * S_ + t] > mean) ? bs : 0.f;
                else if (h == 2) bias = expf(fabsf((float)(t - s)) * (-1.f / (float)S_)) * bs;
                else             bias = (vs * g_v3[b * S_ + t] > 0.5f) ? bs : 0.f;
                vv[q] += bias;
            }
        }
        float m = -INFINITY;
        #pragma unroll
        for (int i = 0; i < 8; i++) m = fmaxf(m, vals[i]);
        m = blockReduceMax(m);
        float sum = 0.f;
        #pragma unroll
        for (int i = 0; i < 8; i++) { vals[i] = expf(vals[i] - m); sum += vals[i]; }
        sum = blockReduceSum(sum);
        float inv = 1.f / sum;
        #pragma unroll
        for (int i = 0; i < 2; i++) {
            int j = tid + i * 256;
            float w0 = vals[i * 4 + 0] * inv, w1 = vals[i * 4 + 1] * inv;
            float w2v = vals[i * 4 + 2] * inv, w3 = vals[i * 4 + 3] * inv;
            w2[2 * j]     = __floats2half2_rn(w0, w1);
            w2[2 * j + 1] = __floats2half2_rn(w2v, w3);
            avg[i * 4 + 0] += w0; avg[i * 4 + 1] += w1;
            avg[i * 4 + 2] += w2v; avg[i * 4 + 3] += w3;
        }
    }

    float4* o4 = (float4*)(outAvg + ((long long)b * S_ + s) * S_);
    #pragma unroll
    for (int i = 0; i < 2; i++) {
        int j = tid + i * 256;
        o4[j] = make_float4(0.25f * avg[i * 4 + 0], 0.25f * avg[i * 4 + 1],
                            0.25f * avg[i * 4 + 2], 0.25f * avg[i * 4 + 3]);
    }
}

__global__ void guilt_kernel(float* __restrict__ outG) {
    int i = blockIdx.x * 256 + threadIdx.x;
    if (i < B_ * S_) outG[i] = 1.0f / (float)S_;
}

// ---------------- bias + residual + LayerNorm ----------------
__global__ __launch_bounds__(256) void ln_kernel(const float* __restrict__ emb,
                                                 const float* __restrict__ Wo_b,
                                                 const float* __restrict__ gam,
                                                 const float* __restrict__ bet,
                                                 float* __restrict__ outp) {
    int tok = blockIdx.x;
    int tid = threadIdx.x;
    float y[4];
    float s1 = 0.f;
    #pragma unroll
    for (int i = 0; i < 4; i++) {
        int d = tid + i * 256;
        y[i] = g_wo[(long long)tok * D_ + d] + Wo_b[d] + emb[(long long)tok * D_ + d];
        s1 += y[i];
    }
    s1 = blockReduceSum(s1);
    float mu = s1 * (1.f / (float)D_);
    float s2 = 0.f;
    #pragma unroll
    for (int i = 0; i < 4; i++) { float dd = y[i] - mu; s2 += dd * dd; }
    s2 = blockReduceSum(s2);
    float inv = rsqrtf(s2 * (1.f / (float)D_) + LN_EPS);
    #pragma unroll
    for (int i = 0; i < 4; i++) {
        int d = tid + i * 256;
        outp[(long long)tok * D_ + d] = (y[i] - mu) * inv * gam[d] + bet[d];
    }
}

// ---------------- launch ----------------
extern "C" void kernel_launch(void* const* d_in, const int* in_sizes, int n_in,
                              void* d_out, int out_size) {
    const float* emb   = (const float*)d_in[0];
    const float* Wq    = (const float*)d_in[1];
    const float* Wk    = (const float*)d_in[2];
    const float* Wv    = (const float*)d_in[3];
    const float* bsc   = (const float*)d_in[4];
    const float* Wo_w  = (const float*)d_in[5];
    const float* Wo_b  = (const float*)d_in[6];
    const float* ln_g  = (const float*)d_in[7];
    const float* ln_b  = (const float*)d_in[8];
    float* out = (float*)d_out;

    float *pS, *pWoO;
    __half *pW, *pQ, *pK, *pVt, *pE, *pWq, *pWk, *pWv, *pWo, *pC;
    cudaGetSymbolAddress((void**)&pS,   g_S);
    cudaGetSymbolAddress((void**)&pW,   g_W);
    cudaGetSymbolAddress((void**)&pQ,   g_Q);
    cudaGetSymbolAddress((void**)&pK,   g_K);
    cudaGetSymbolAddress((void**)&pVt,  g_Vt);
    cudaGetSymbolAddress((void**)&pE,   g_E);
    cudaGetSymbolAddress((void**)&pWq,  g_Wq);
    cudaGetSymbolAddress((void**)&pWk,  g_Wk);
    cudaGetSymbolAddress((void**)&pWv,  g_Wv);
    cudaGetSymbolAddress((void**)&pWo,  g_Wo);
    cudaGetSymbolAddress((void**)&pC,   g_C);
    cudaGetSymbolAddress((void**)&pWoO, g_wo);

    const long long SD  = (long long)S_ * D_;
    const long long SH  = (long long)S_ * HD_;
    const long long SS  = (long long)S_ * S_;
    const long long EP  = (long long)B_ * SD;
    const long long WQP = (long long)H_ * HD_ * HD_;
    const long long WOP = (long long)D_ * D_;

    const int DSMEM = 3 * (int)STG_SZ;   // 144KB
    cudaFuncSetAttribute(mma_gemm, cudaFuncAttributeMaxDynamicSharedMemorySize, DSMEM);

    dim3 blk(256);

    // fp32 -> fp16 conversions
    cvt_kernel<<<(unsigned)(EP / 8 / 256), blk>>>(emb, pE);
    cvt_kernel<<<(unsigned)(WQP / 8 / 256), blk>>>(Wq, pWq);
    cvt_kernel<<<(unsigned)(WQP / 8 / 256), blk>>>(Wk, pWk);
    cvt_kernel<<<(unsigned)(WQP / 8 / 256), blk>>>(Wv, pWv);
    cvt_kernel<<<(unsigned)(WOP / 8 / 256), blk>>>(Wo_w, pWo);

    // Q = X @ Wq^T -> fp16 [b,h,s,e]   (N=256 in one block column)
    mma_gemm<<<dim3(1, 16, 16), blk, DSMEM>>>(pE, D_, SD, HD_,
        pWq, HD_, 0, (long long)HD_ * HD_,
        pS /*unused*/, pQ, (long long)H_ * SH, SH, HD_, 1, HD_, 1.0f, H_, 1);
    // K
    mma_gemm<<<dim3(1, 16, 16), blk, DSMEM>>>(pE, D_, SD, HD_,
        pWk, HD_, 0, (long long)HD_ * HD_,
        pS, pK, (long long)H_ * SH, SH, HD_, 1, HD_, 1.0f, H_, 1);
    // V, stored transposed [b,h,e,t]
    mma_gemm<<<dim3(1, 16, 16), blk, DSMEM>>>(pE, D_, SD, HD_,
        pWv, HD_, 0, (long long)HD_ * HD_,
        pS, pVt, (long long)H_ * HD_ * S_, (long long)HD_ * S_, 1, S_, HD_, 1.0f, H_, 1);

    // mag1 / v3 / intent mean
    mag_kernel<<<B_ * S_, blk>>>(emb);
    mean_kernel<<<1, blk>>>();

    // scores = (Q @ K^T) / 16 -> fp32 g_S
    mma_gemm<<<dim3(8, 16, 16), blk, DSMEM>>>(pQ, HD_, (long long)H_ * SH, SH,
        pK, HD_, (long long)H_ * SH, SH,
        pS, pW /*unused*/, (long long)H_ * SS, SS, S_, 1, HD_, 0.0625f, H_, 0);

    // + biases, softmax -> fp16 weights, fused head-average -> output region 1
    softmax_avg_kernel<<<dim3(S_, B_), blk>>>(bsc, out + EP);
    guilt_kernel<<<(B_ * S_ + 255) / 256, blk>>>(out + EP + (long long)B_ * SS);

    // attended = W @ V -> concat fp16 [b,s,h*hd+e]   (W read exactly once)
    mma_gemm<<<dim3(1, 16, 16), blk, DSMEM>>>(pW, S_, (long long)H_ * SS, SS,
        pVt, S_, (long long)H_ * HD_ * S_, (long long)HD_ * S_,
        pS, pC, SD, HD_, D_, 1, S_, 1.0f, H_, 1);

    // out_pre = concat @ Wo^T -> fp32 g_wo
    mma_gemm<<<dim3(4, 64, 1), blk, DSMEM>>>(pC, D_, 0, 0,
        pWo, D_, 0, 0,
        pWoO, pC /*unused*/, 0, 0, D_, 1, D_, 1.0f, 1, 0);

    // + Wo_b + residual + LayerNorm -> output region 0
    ln_kernel<<<B_ * S_, blk>>>(emb, Wo_b, ln_g, ln_b, out);
}

// round 13
// speedup vs baseline: 5.1923x; 1.0365x over previous
#include <cuda_runtime.h>
#include <cuda_fp16.h>
#include <math.h>

#define B_  4
#define S_  2048
#define D_  1024
#define H_  4
#define HD_ 256
#define LN_EPS 1e-5f

typedef unsigned int       u32;
typedef unsigned long long u64;

// ---------------- device scratch (no cudaMalloc allowed) ----------------
__device__ __align__(16) float  g_S [(size_t)B_*H_*S_*S_];     // fp32 scores
__device__ __align__(16) __half g_W [(size_t)B_*H_*S_*S_];     // softmax weights fp16
__device__ __align__(16) __half g_Q [(size_t)B_*H_*S_*HD_];
__device__ __align__(16) __half g_K [(size_t)B_*H_*S_*HD_];
__device__ __align__(16) __half g_Vt[(size_t)B_*H_*HD_*S_];    // V transposed [b,h,e,t]
__device__ __align__(16) __half g_E [(size_t)B_*S_*D_];        // emb fp16
__device__ __align__(16) __half g_Wq[(size_t)H_*HD_*HD_];
__device__ __align__(16) __half g_Wk[(size_t)H_*HD_*HD_];
__device__ __align__(16) __half g_Wv[(size_t)H_*HD_*HD_];
__device__ __align__(16) __half g_Wo[(size_t)D_*D_];
__device__ __align__(16) __half g_C [(size_t)B_*S_*D_];        // concat fp16
__device__ __align__(16) float  g_wo[(size_t)B_*S_*D_];        // Wo output pre-LN
__device__ float g_mag1[B_*S_];
__device__ float g_v3[B_*S_];
__device__ float g_mean;

// ---------------- helpers ----------------
__device__ __forceinline__ u32 smem_to_u32(const void* p) {
    u32 a;
    asm("{ .reg .u64 t; cvta.to.shared.u64 t, %1; cvt.u32.u64 %0, t; }" : "=r"(a) : "l"(p));
    return a;
}
static __device__ __forceinline__ u32 swz(u32 o) { return o ^ ((o >> 3) & 0x70u); }

__device__ __forceinline__ void cp_async16(u32 dst, const void* src) {
    asm volatile("cp.async.cg.shared.global [%0], [%1], 16;" :: "r"(dst), "l"(src));
}
#define CP_COMMIT()  asm volatile("cp.async.commit_group;" ::: "memory")
#define CP_WAIT(N)   asm volatile("cp.async.wait_group %0;" :: "n"(N) : "memory")

__device__ __forceinline__ void ldsm4(u32 addr, u32& r0, u32& r1, u32& r2, u32& r3) {
    asm volatile("ldmatrix.sync.aligned.m8n8.x4.shared.b16 {%0,%1,%2,%3}, [%4];"
        : "=r"(r0), "=r"(r1), "=r"(r2), "=r"(r3) : "r"(addr));
}
__device__ __forceinline__ void mma16816(float* c, const u32* a, u32 b0, u32 b1) {
    asm volatile("mma.sync.aligned.m16n8k16.row.col.f32.f16.f16.f32 "
        "{%0,%1,%2,%3}, {%4,%5,%6,%7}, {%8,%9}, {%0,%1,%2,%3};"
        : "+f"(c[0]), "+f"(c[1]), "+f"(c[2]), "+f"(c[3])
        : "r"(a[0]), "r"(a[1]), "r"(a[2]), "r"(a[3]), "r"(b0), "r"(b1));
}

// ============================================================================
// Batched NT GEMM via fp16 mma.sync: C = alpha * (A @ B^T). Template on BN.
// BN=128: stage 32KB, 3 stages, 2 CTAs/SM (latency hiding via co-residency).
// BN=256: stage 48KB, 3 stages, 1 CTA/SM (for long-K GEMMs where A is huge and
//         must be read once: grid.x=1 covers all N in one block column).
// A: [M,K] rows K-major, stride lda. B: [N,K] rows K-major, stride ldb.
// K-chunk 64. Stage: A @0 (16KB), B @16K (BN*128 B); 128B rows, SW128.
// 8 warps: wm=wid&3 (4 x 32 rows), wn=wid>>2 (2 x BN/2 cols).
// Output: outHalf ? fp16 Ch : fp32 Cf; element (m,n) at m*Crs + n*Ccs.
// Requires M%128==0, N%BN==0, K%64==0, K/64 >= 3.
// ============================================================================
template<int BN>
__device__ __forceinline__ void stage_load(u32 sbase, int buf,
    const __half* A, int lda, int m0,
    const __half* Bm, int ldb, int n0,
    long long kof, int tid)
{
    const u32 STG = 16384u + (u32)BN * 128u;
    const int ITERS = (1024 + BN * 8) / 256;
    #pragma unroll
    for (int it = 0; it < ITERS; it++) {
        int idx = tid + it * 256;
        const __half* src;
        u32 dst;
        if (idx < 1024) {                            // A: 128 rows x 8 chunks
            int r = idx >> 3, c = idx & 7;
            src = A + (long long)(m0 + r) * lda + kof + c * 8;
            dst = sbase + (u32)buf * STG + swz((u32)(r * 128 + c * 16));
        } else {                                     // B: BN rows x 8 chunks
            int j = idx - 1024;
            int r = j >> 3, c = j & 7;
            src = Bm + (long long)(n0 + r) * ldb + kof + c * 8;
            dst = sbase + (u32)buf * STG + 16384u + swz((u32)(r * 128 + c * 16));
        }
        cp_async16(dst, src);
    }
    CP_COMMIT();
}

template<int BN>
__global__ void __launch_bounds__(256, BN == 128 ? 2 : 1)
mma_gemm(const __half* __restrict__ A, int lda, long long Asb, long long Ash,
         const __half* __restrict__ Bm, int ldb, long long Bsb, long long Bsh,
         float* __restrict__ Cf, __half* __restrict__ Ch,
         long long Csb, long long Csh, long long Crs, long long Ccs,
         int K, float alpha, int Hdiv, int outHalf)
{
    extern __shared__ __align__(16) char smem[];
    const u32 sbase = smem_to_u32(smem);
    const u32 STG = 16384u + (u32)BN * 128u;
    const int NQ = BN / 32;          // 16-row B groups per warp (4 or 8)
    const int NF = BN / 16;          // 8-col accum fragments per warp (8 or 16)

    int tid = threadIdx.x, lane = tid & 31, wid = tid >> 5;
    int wm = wid & 3, wn = wid >> 2;                 // warp tile 32 x BN/2
    int z = blockIdx.z, b = z / Hdiv, h = z % Hdiv;
    A  += b * Asb + h * Ash;
    Bm += b * Bsb + h * Bsh;
    const long long Cb = b * Csb + h * Csh;

    const int m0 = blockIdx.y * 128, n0 = blockIdx.x * BN;

    const int ph_row  = (lane & 7) + ((lane >> 3) & 1) * 8;
    const int ph_byte = (lane >> 4) * 16;

    float acc[2][BN / 16][4];
    #pragma unroll
    for (int i = 0; i < 2; i++)
        #pragma unroll
        for (int j = 0; j < NF; j++)
            #pragma unroll
            for (int k = 0; k < 4; k++) acc[i][j][k] = 0.f;

    const int nc = K >> 6;
    stage_load<BN>(sbase, 0, A, lda, m0, Bm, ldb, n0, 0,   tid);
    stage_load<BN>(sbase, 1, A, lda, m0, Bm, ldb, n0, 64,  tid);
    stage_load<BN>(sbase, 2, A, lda, m0, Bm, ldb, n0, 128, tid);

    int buf = 0;
    for (int ci = 0; ci < nc; ci++) {
        CP_WAIT(2);
        __syncthreads();

        u32 sb = sbase + (u32)buf * STG;
        #pragma unroll
        for (int ks = 0; ks < 4; ks++) {
            u32 afr[2][4];
            #pragma unroll
            for (int mh = 0; mh < 2; mh++) {
                int row = wm * 32 + mh * 16 + ph_row;
                u32 ad = sb + swz((u32)(row * 128 + ks * 32 + ph_byte));
                ldsm4(ad, afr[mh][0], afr[mh][1], afr[mh][2], afr[mh][3]);
            }
            u32 bfr[BN / 32][4];
            #pragma unroll
            for (int nq = 0; nq < NQ; nq++) {
                int row = wn * (BN / 2) + nq * 16 + ph_row;
                u32 ad = sb + 16384u + swz((u32)(row * 128 + ks * 32 + ph_byte));
                ldsm4(ad, bfr[nq][0], bfr[nq][1], bfr[nq][2], bfr[nq][3]);
            }
            #pragma unroll
            for (int mh = 0; mh < 2; mh++)
                #pragma unroll
                for (int nq = 0; nq < NQ; nq++) {
                    mma16816(acc[mh][nq * 2 + 0], afr[mh], bfr[nq][0], bfr[nq][2]);
                    mma16816(acc[mh][nq * 2 + 1], afr[mh], bfr[nq][1], bfr[nq][3]);
                }
        }
        __syncthreads();
        if (ci + 3 < nc)
            stage_load<BN>(sbase, buf, A, lda, m0, Bm, ldb, n0, (long long)(ci + 3) * 64, tid);
        else
            CP_COMMIT();                             // keep wait count aligned
        buf = (buf == 2) ? 0 : buf + 1;
    }

    // epilogue: d-frag lane map: rows lane>>2 (+8), cols (lane&3)*2 (+1)
    #pragma unroll
    for (int mh = 0; mh < 2; mh++)
        #pragma unroll
        for (int nf = 0; nf < NF; nf++) {
            float* c = acc[mh][nf];
            long long mA = m0 + wm * 32 + mh * 16 + (lane >> 2);
            long long nA = n0 + wn * (BN / 2) + nf * 8 + (lane & 3) * 2;
            if (Ccs == 1) {
                #pragma unroll
                for (int qr = 0; qr < 2; qr++) {
                    long long m = mA + qr * 8;
                    long long co = Cb + m * Crs + nA;
                    float v0 = alpha * c[qr * 2 + 0], v1 = alpha * c[qr * 2 + 1];
                    if (outHalf) *(__half2*)(Ch + co) = __floats2half2_rn(v0, v1);
                    else         *(float2*)(Cf + co) = make_float2(v0, v1);
                }
            } else {                                 // Crs==1 (Vt): scalar stores
                #pragma unroll
                for (int q = 0; q < 4; q++) {
                    long long m = mA + (q >> 1) * 8;
                    long long n = nA + (q & 1);
                    float v = alpha * c[q];
                    long long co = Cb + m + n * Ccs;
                    if (outHalf) Ch[co] = __float2half_rn(v);
                    else         Cf[co] = v;
                }
            }
        }
}

// ---------------- fp32 -> fp16 conversion (8 elems/thread) ----------------
__global__ __launch_bounds__(256) void cvt_kernel(const float* __restrict__ x,
                                                  __half* __restrict__ y) {
    long long i = (long long)blockIdx.x * 256 + threadIdx.x;
    float4 a = ((const float4*)x)[2 * i];
    float4 b = ((const float4*)x)[2 * i + 1];
    __half2 h0 = __floats2half2_rn(a.x, a.y);
    __half2 h1 = __floats2half2_rn(a.z, a.w);
    __half2 h2 = __floats2half2_rn(b.x, b.y);
    __half2 h3 = __floats2half2_rn(b.z, b.w);
    uint4 o;
    o.x = *(u32*)&h0; o.y = *(u32*)&h1; o.z = *(u32*)&h2; o.w = *(u32*)&h3;
    ((uint4*)y)[i] = o;
}

// ---------------- block reductions ----------------
__device__ __forceinline__ float blockReduceSum(float v) {
    __shared__ float sh[33];
    __syncthreads();
    #pragma unroll
    for (int o = 16; o; o >>= 1) v += __shfl_xor_sync(0xffffffffu, v, o);
    if ((threadIdx.x & 31) == 0) sh[threadIdx.x >> 5] = v;
    __syncthreads();
    if (threadIdx.x < 32) {
        v = (threadIdx.x < (blockDim.x >> 5)) ? sh[threadIdx.x] : 0.f;
        #pragma unroll
        for (int o = 16; o; o >>= 1) v += __shfl_xor_sync(0xffffffffu, v, o);
        if (threadIdx.x == 0) sh[32] = v;
    }
    __syncthreads();
    return sh[32];
}
__device__ __forceinline__ float blockReduceMax(float v) {
    __shared__ float sh[33];
    __syncthreads();
    #pragma unroll
    for (int o = 16; o; o >>= 1) v = fmaxf(v, __shfl_xor_sync(0xffffffffu, v, o));
    if ((threadIdx.x & 31) == 0) sh[threadIdx.x >> 5] = v;
    __syncthreads();
    if (threadIdx.x < 32) {
        v = (threadIdx.x < (blockDim.x >> 5)) ? sh[threadIdx.x] : -INFINITY;
        #pragma unroll
        for (int o = 16; o; o >>= 1) v = fmaxf(v, __shfl_xor_sync(0xffffffffu, v, o));
        if (threadIdx.x == 0) sh[32] = v;
    }
    __syncthreads();
    return sh[32];
}

// ---------------- mag1 / v3 ----------------
__global__ __launch_bounds__(256) void mag_kernel(const float* __restrict__ emb) {
    int row = blockIdx.x;
    int tid = threadIdx.x;
    float v = emb[(long long)row * D_ + HD_ + tid];
    float ss = blockReduceSum(v * v);
    if (tid == 0) {
        g_mag1[row] = sqrtf(ss);
        g_v3[row]   = emb[(long long)row * D_ + (D_ - 1)];
    }
}
__global__ __launch_bounds__(256) void mean_kernel() {
    int tid = threadIdx.x;
    float acc = 0.f;
    for (int b = 0; b < B_; b++) {
        float v = 0.f;
        for (int i = tid; i < S_; i += 256) v += g_mag1[b * S_ + i];
        v = blockReduceSum(v);
        acc += v * v;
    }
    if (tid == 0) g_mean = acc / ((float)B_ * (float)S_ * (float)S_);
}

// ---------------- bias + softmax over all 4 heads + fused head-average ----------------
__global__ __launch_bounds__(256) void softmax_avg_kernel(const float* __restrict__ bias_scalars,
                                                          float* __restrict__ outAvg) {
    int s = blockIdx.x, b = blockIdx.y;
    int tid = threadIdx.x;
    float mean = g_mean;
    float ms = g_mag1[b * S_ + s];
    float vs = g_v3[b * S_ + s];

    float avg[8];
    #pragma unroll
    for (int q = 0; q < 8; q++) avg[q] = 0.f;

    #pragma unroll
    for (int h = 0; h < H_; h++) {
        const long long roff = (((long long)(b * H_ + h)) * S_ + s) * S_;
        const float4* row4 = (const float4*)(g_S + roff);
        __half2* w2 = (__half2*)(g_W + roff);
        float bs = bias_scalars[h];

        float vals[8];
        #pragma unroll
        for (int i = 0; i < 2; i++) {
            int j = tid + i * 256;
            float4 x = row4[j];
            int t0 = 4 * j;
            float* vv = vals + i * 4;
            vv[0] = x.x; vv[1] = x.y; vv[2] = x.z; vv[3] = x.w;
            #pragma unroll
            for (int q = 0; q < 4; q++) {
                int t = t0 + q;
                float bias;
                if (h == 0)      bias = (t > s) ? bs : 0.f;
                else if (h == 1) bias = (ms * g_mag1[b * S_ + t] > mean) ? bs : 0.f;
                else if (h == 2) bias = expf(fabsf((float)(t - s)) * (-1.f / (float)S_)) * bs;
                else             bias = (vs * g_v3[b * S_ + t] > 0.5f) ? bs : 0.f;
                vv[q] += bias;
            }
        }
        float m = -INFINITY;
        #pragma unroll
        for (int i = 0; i < 8; i++) m = fmaxf(m, vals[i]);
        m = blockReduceMax(m);
        float sum = 0.f;
        #pragma unroll
        for (int i = 0; i < 8; i++) { vals[i] = expf(vals[i] - m); sum += vals[i]; }
        sum = blockReduceSum(sum);
        float inv = 1.f / sum;
        #pragma unroll
        for (int i = 0; i < 2; i++) {
            int j = tid + i * 256;
            float w0 = vals[i * 4 + 0] * inv, w1 = vals[i * 4 + 1] * inv;
            float w2v = vals[i * 4 + 2] * inv, w3 = vals[i * 4 + 3] * inv;
            w2[2 * j]     = __floats2half2_rn(w0, w1);
            w2[2 * j + 1] = __floats2half2_rn(w2v, w3);
            avg[i * 4 + 0] += w0; avg[i * 4 + 1] += w1;
            avg[i * 4 + 2] += w2v; avg[i * 4 + 3] += w3;
        }
    }

    float4* o4 = (float4*)(outAvg + ((long long)b * S_ + s) * S_);
    #pragma unroll
    for (int i = 0; i < 2; i++) {
        int j = tid + i * 256;
        o4[j] = make_float4(0.25f * avg[i * 4 + 0], 0.25f * avg[i * 4 + 1],
                            0.25f * avg[i * 4 + 2], 0.25f * avg[i * 4 + 3]);
    }
}

__global__ void guilt_kernel(float* __restrict__ outG) {
    int i = blockIdx.x * 256 + threadIdx.x;
    if (i < B_ * S_) outG[i] = 1.0f / (float)S_;
}

// ---------------- bias + residual + LayerNorm ----------------
__global__ __launch_bounds__(256) void ln_kernel(const float* __restrict__ emb,
                                                 const float* __restrict__ Wo_b,
                                                 const float* __restrict__ gam,
                                                 const float* __restrict__ bet,
                                                 float* __restrict__ outp) {
    int tok = blockIdx.x;
    int tid = threadIdx.x;
    float y[4];
    float s1 = 0.f;
    #pragma unroll
    for (int i = 0; i < 4; i++) {
        int d = tid + i * 256;
        y[i] = g_wo[(long long)tok * D_ + d] + Wo_b[d] + emb[(long long)tok * D_ + d];
        s1 += y[i];
    }
    s1 = blockReduceSum(s1);
    float mu = s1 * (1.f / (float)D_);
    float s2 = 0.f;
    #pragma unroll
    for (int i = 0; i < 4; i++) { float dd = y[i] - mu; s2 += dd * dd; }
    s2 = blockReduceSum(s2);
    float inv = rsqrtf(s2 * (1.f / (float)D_) + LN_EPS);
    #pragma unroll
    for (int i = 0; i < 4; i++) {
        int d = tid + i * 256;
        outp[(long long)tok * D_ + d] = (y[i] - mu) * inv * gam[d] + bet[d];
    }
}

// ---------------- launch ----------------
extern "C" void kernel_launch(void* const* d_in, const int* in_sizes, int n_in,
                              void* d_out, int out_size) {
    const float* emb   = (const float*)d_in[0];
    const float* Wq    = (const float*)d_in[1];
    const float* Wk    = (const float*)d_in[2];
    const float* Wv    = (const float*)d_in[3];
    const float* bsc   = (const float*)d_in[4];
    const float* Wo_w  = (const float*)d_in[5];
    const float* Wo_b  = (const float*)d_in[6];
    const float* ln_g  = (const float*)d_in[7];
    const float* ln_b  = (const float*)d_in[8];
    float* out = (float*)d_out;

    float *pS, *pWoO;
    __half *pW, *pQ, *pK, *pVt, *pE, *pWq, *pWk, *pWv, *pWo, *pC;
    cudaGetSymbolAddress((void**)&pS,   g_S);
    cudaGetSymbolAddress((void**)&pW,   g_W);
    cudaGetSymbolAddress((void**)&pQ,   g_Q);
    cudaGetSymbolAddress((void**)&pK,   g_K);
    cudaGetSymbolAddress((void**)&pVt,  g_Vt);
    cudaGetSymbolAddress((void**)&pE,   g_E);
    cudaGetSymbolAddress((void**)&pWq,  g_Wq);
    cudaGetSymbolAddress((void**)&pWk,  g_Wk);
    cudaGetSymbolAddress((void**)&pWv,  g_Wv);
    cudaGetSymbolAddress((void**)&pWo,  g_Wo);
    cudaGetSymbolAddress((void**)&pC,   g_C);
    cudaGetSymbolAddress((void**)&pWoO, g_wo);

    const long long SD  = (long long)S_ * D_;
    const long long SH  = (long long)S_ * HD_;
    const long long SS  = (long long)S_ * S_;
    const long long EP  = (long long)B_ * SD;
    const long long WQP = (long long)H_ * HD_ * HD_;
    const long long WOP = (long long)D_ * D_;

    const int DSMEM_N = 3 * 32768;   // narrow: 96KB, 2 CTAs/SM
    const int DSMEM_W = 3 * 49152;   // wide:  144KB, 1 CTA/SM
    cudaFuncSetAttribute(mma_gemm<128>, cudaFuncAttributeMaxDynamicSharedMemorySize, DSMEM_N);
    cudaFuncSetAttribute(mma_gemm<256>, cudaFuncAttributeMaxDynamicSharedMemorySize, DSMEM_W);

    dim3 blk(256);

    // fp32 -> fp16 conversions
    cvt_kernel<<<(unsigned)(EP / 8 / 256), blk>>>(emb, pE);
    cvt_kernel<<<(unsigned)(WQP / 8 / 256), blk>>>(Wq, pWq);
    cvt_kernel<<<(unsigned)(WQP / 8 / 256), blk>>>(Wk, pWk);
    cvt_kernel<<<(unsigned)(WQP / 8 / 256), blk>>>(Wv, pWv);
    cvt_kernel<<<(unsigned)(WOP / 8 / 256), blk>>>(Wo_w, pWo);

    // Q = X @ Wq^T -> fp16 [b,h,s,e]   (narrow, 2 CTAs/SM)
    mma_gemm<128><<<dim3(2, 16, 16), blk, DSMEM_N>>>(pE, D_, SD, HD_,
        pWq, HD_, 0, (long long)HD_ * HD_,
        pS /*unused*/, pQ, (long long)H_ * SH, SH, HD_, 1, HD_, 1.0f, H_, 1);
    // K
    mma_gemm<128><<<dim3(2, 16, 16), blk, DSMEM_N>>>(pE, D_, SD, HD_,
        pWk, HD_, 0, (long long)HD_ * HD_,
        pS, pK, (long long)H_ * SH, SH, HD_, 1, HD_, 1.0f, H_, 1);
    // V, stored transposed [b,h,e,t]
    mma_gemm<128><<<dim3(2, 16, 16), blk, DSMEM_N>>>(pE, D_, SD, HD_,
        pWv, HD_, 0, (long long)HD_ * HD_,
        pS, pVt, (long long)H_ * HD_ * S_, (long long)HD_ * S_, 1, S_, HD_, 1.0f, H_, 1);

    // mag1 / v3 / intent mean
    mag_kernel<<<B_ * S_, blk>>>(emb);
    mean_kernel<<<1, blk>>>();

    // scores = (Q @ K^T) / 16 -> fp32 g_S   (narrow: short K, needs co-residency)
    mma_gemm<128><<<dim3(16, 16, 16), blk, DSMEM_N>>>(pQ, HD_, (long long)H_ * SH, SH,
        pK, HD_, (long long)H_ * SH, SH,
        pS, pW /*unused*/, (long long)H_ * SS, SS, S_, 1, HD_, 0.0625f, H_, 0);

    // + biases, softmax -> fp16 weights, fused head-average -> output region 1
    softmax_avg_kernel<<<dim3(S_, B_), blk>>>(bsc, out + EP);
    guilt_kernel<<<(B_ * S_ + 255) / 256, blk>>>(out + EP + (long long)B_ * SS);

    // attended = W @ V -> concat fp16   (wide: K=2048, W read exactly once)
    mma_gemm<256><<<dim3(1, 16, 16), blk, DSMEM_W>>>(pW, S_, (long long)H_ * SS, SS,
        pVt, S_, (long long)H_ * HD_ * S_, (long long)HD_ * S_,
        pS, pC, SD, HD_, D_, 1, S_, 1.0f, H_, 1);

    // out_pre = concat @ Wo^T -> fp32 g_wo   (narrow)
    mma_gemm<128><<<dim3(8, 64, 1), blk, DSMEM_N>>>(pC, D_, 0, 0,
        pWo, D_, 0, 0,
        pWoO, pC /*unused*/, 0, 0, D_, 1, D_, 1.0f, 1, 0);

    // + Wo_b + residual + LayerNorm -> output region 0
    ln_kernel<<<B_ * S_, blk>>>(emb, Wo_b, ln_g, ln_b, out);
}

// round 15
// speedup vs baseline: 5.2181x; 1.0050x over previous
#include <cuda_runtime.h>
#include <cuda_fp16.h>
#include <math.h>

#define B_  4
#define S_  2048
#define D_  1024
#define H_  4
#define HD_ 256
#define LN_EPS 1e-5f

typedef unsigned int       u32;
typedef unsigned long long u64;

// ---------------- device scratch (no cudaMalloc allowed) ----------------
__device__ __align__(16) __half g_W [(size_t)B_*H_*S_*S_];     // unnormalized exp(score+bias), fp16
__device__ __align__(16) __half g_Q [(size_t)B_*H_*S_*HD_];
__device__ __align__(16) __half g_K [(size_t)B_*H_*S_*HD_];
__device__ __align__(16) __half g_Vt[(size_t)B_*H_*HD_*S_];    // V transposed [b,h,e,t]
__device__ __align__(16) __half g_E [(size_t)B_*S_*D_];        // emb fp16
__device__ __align__(16) __half g_Wq[(size_t)H_*HD_*HD_];
__device__ __align__(16) __half g_Wk[(size_t)H_*HD_*HD_];
__device__ __align__(16) __half g_Wv[(size_t)H_*HD_*HD_];
__device__ __align__(16) __half g_Wo[(size_t)D_*D_];
__device__ __align__(16) __half g_C [(size_t)B_*S_*D_];        // concat fp16
__device__ __align__(16) float  g_wo[(size_t)B_*S_*D_];        // Wo output pre-LN
__device__ __align__(16) float  g_invR[B_*H_*S_];              // 1 / row-sum of exp
__device__ __align__(16) float  g_prox[S_];                    // exp(-d/S) table
__device__ float g_mag1[B_*S_];
__device__ float g_v3[B_*S_];
__device__ float g_mean;

// ---------------- helpers ----------------
__device__ __forceinline__ u32 smem_to_u32(const void* p) {
    u32 a;
    asm("{ .reg .u64 t; cvta.to.shared.u64 t, %1; cvt.u32.u64 %0, t; }" : "=r"(a) : "l"(p));
    return a;
}
static __device__ __forceinline__ u32 swz(u32 o) { return o ^ ((o >> 3) & 0x70u); }

__device__ __forceinline__ void cp_async16(u32 dst, const void* src) {
    asm volatile("cp.async.cg.shared.global [%0], [%1], 16;" :: "r"(dst), "l"(src));
}
#define CP_COMMIT()  asm volatile("cp.async.commit_group;" ::: "memory")
#define CP_WAIT(N)   asm volatile("cp.async.wait_group %0;" :: "n"(N) : "memory")

__device__ __forceinline__ void ldsm4(u32 addr, u32& r0, u32& r1, u32& r2, u32& r3) {
    asm volatile("ldmatrix.sync.aligned.m8n8.x4.shared.b16 {%0,%1,%2,%3}, [%4];"
        : "=r"(r0), "=r"(r1), "=r"(r2), "=r"(r3) : "r"(addr));
}
__device__ __forceinline__ void mma16816(float* c, const u32* a, u32 b0, u32 b1) {
    asm volatile("mma.sync.aligned.m16n8k16.row.col.f32.f16.f16.f32 "
        "{%0,%1,%2,%3}, {%4,%5,%6,%7}, {%8,%9}, {%0,%1,%2,%3};"
        : "+f"(c[0]), "+f"(c[1]), "+f"(c[2]), "+f"(c[3])
        : "r"(a[0]), "r"(a[1]), "r"(a[2]), "r"(a[3]), "r"(b0), "r"(b1));
}

// ============================================================================
// Batched NT GEMM via fp16 mma.sync: C = alpha * (A @ B^T). Template on BN.
// BN=128: stage 32KB, 3 stages, 2 CTAs/SM. BN=256: stage 48KB, 1 CTA/SM.
// emode: 0 = fp32 out; 1 = fp16 out (optionally scaled per-row by rowScale);
//        2 = fp16 exp(score + legal-bias) out (uses g_mag1/g_v3/g_mean/g_prox).
// ============================================================================
template<int BN>
__device__ __forceinline__ void stage_load(u32 sbase, int buf,
    const __half* A, int lda, int m0,
    const __half* Bm, int ldb, int n0,
    long long kof, int tid)
{
    const u32 STG = 16384u + (u32)BN * 128u;
    const int ITERS = (1024 + BN * 8) / 256;
    #pragma unroll
    for (int it = 0; it < ITERS; it++) {
        int idx = tid + it * 256;
        const __half* src;
        u32 dst;
        if (idx < 1024) {                            // A: 128 rows x 8 chunks
            int r = idx >> 3, c = idx & 7;
            src = A + (long long)(m0 + r) * lda + kof + c * 8;
            dst = sbase + (u32)buf * STG + swz((u32)(r * 128 + c * 16));
        } else {                                     // B: BN rows x 8 chunks
            int j = idx - 1024;
            int r = j >> 3, c = j & 7;
            src = Bm + (long long)(n0 + r) * ldb + kof + c * 8;
            dst = sbase + (u32)buf * STG + 16384u + swz((u32)(r * 128 + c * 16));
        }
        cp_async16(dst, src);
    }
    CP_COMMIT();
}

template<int BN>
__global__ void __launch_bounds__(256, BN == 128 ? 2 : 1)
mma_gemm(const __half* __restrict__ A, int lda, long long Asb, long long Ash,
         const __half* __restrict__ Bm, int ldb, long long Bsb, long long Bsh,
         float* __restrict__ Cf, __half* __restrict__ Ch,
         long long Csb, long long Csh, long long Crs, long long Ccs,
         int K, float alpha, int Hdiv, int emode,
         const float* __restrict__ Bsc, const float* __restrict__ rowScale)
{
    extern __shared__ __align__(16) char smem[];
    const u32 sbase = smem_to_u32(smem);
    const u32 STG = 16384u + (u32)BN * 128u;
    const int NQ = BN / 32;
    const int NF = BN / 16;

    int tid = threadIdx.x, lane = tid & 31, wid = tid >> 5;
    int wm = wid & 3, wn = wid >> 2;                 // warp tile 32 x BN/2
    int z = blockIdx.z, b = z / Hdiv, h = z % Hdiv;
    A  += b * Asb + h * Ash;
    Bm += b * Bsb + h * Bsh;
    const long long Cb = b * Csb + h * Csh;

    const int m0 = blockIdx.y * 128, n0 = blockIdx.x * BN;

    const int ph_row  = (lane & 7) + ((lane >> 3) & 1) * 8;
    const int ph_byte = (lane >> 4) * 16;

    float acc[2][BN / 16][4];
    #pragma unroll
    for (int i = 0; i < 2; i++)
        #pragma unroll
        for (int j = 0; j < NF; j++)
            #pragma unroll
            for (int k = 0; k < 4; k++) acc[i][j][k] = 0.f;

    const int nc = K >> 6;
    stage_load<BN>(sbase, 0, A, lda, m0, Bm, ldb, n0, 0,   tid);
    stage_load<BN>(sbase, 1, A, lda, m0, Bm, ldb, n0, 64,  tid);
    stage_load<BN>(sbase, 2, A, lda, m0, Bm, ldb, n0, 128, tid);

    int buf = 0;
    for (int ci = 0; ci < nc; ci++) {
        CP_WAIT(2);
        __syncthreads();

        u32 sb = sbase + (u32)buf * STG;
        #pragma unroll
        for (int ks = 0; ks < 4; ks++) {
            u32 afr[2][4];
            #pragma unroll
            for (int mh = 0; mh < 2; mh++) {
                int row = wm * 32 + mh * 16 + ph_row;
                u32 ad = sb + swz((u32)(row * 128 + ks * 32 + ph_byte));
                ldsm4(ad, afr[mh][0], afr[mh][1], afr[mh][2], afr[mh][3]);
            }
            u32 bfr[BN / 32][4];
            #pragma unroll
            for (int nq = 0; nq < NQ; nq++) {
                int row = wn * (BN / 2) + nq * 16 + ph_row;
                u32 ad = sb + 16384u + swz((u32)(row * 128 + ks * 32 + ph_byte));
                ldsm4(ad, bfr[nq][0], bfr[nq][1], bfr[nq][2], bfr[nq][3]);
            }
            #pragma unroll
            for (int mh = 0; mh < 2; mh++)
                #pragma unroll
                for (int nq = 0; nq < NQ; nq++) {
                    mma16816(acc[mh][nq * 2 + 0], afr[mh], bfr[nq][0], bfr[nq][2]);
                    mma16816(acc[mh][nq * 2 + 1], afr[mh], bfr[nq][1], bfr[nq][3]);
                }
        }
        __syncthreads();
        if (ci + 3 < nc)
            stage_load<BN>(sbase, buf, A, lda, m0, Bm, ldb, n0, (long long)(ci + 3) * 64, tid);
        else
            CP_COMMIT();
        buf = (buf == 2) ? 0 : buf + 1;
    }

    // epilogue context for exp/bias mode
    float bs_ = 0.f, meanv = 0.f;
    if (emode == 2) { bs_ = Bsc[h]; meanv = g_mean; }

    #pragma unroll
    for (int mh = 0; mh < 2; mh++)
        #pragma unroll
        for (int nf = 0; nf < NF; nf++) {
            float* c = acc[mh][nf];
            long long mA = m0 + wm * 32 + mh * 16 + (lane >> 2);
            long long nA = n0 + wn * (BN / 2) + nf * 8 + (lane & 3) * 2;
            if (Ccs == 1) {
                #pragma unroll
                for (int qr = 0; qr < 2; qr++) {
                    long long m = mA + qr * 8;
                    long long co = Cb + m * Crs + nA;
                    float v0 = alpha * c[qr * 2 + 0], v1 = alpha * c[qr * 2 + 1];
                    if (emode == 2) {
                        int si = (int)m, ti = (int)nA;
                        float bias0, bias1;
                        if (h == 0) {
                            bias0 = (ti > si) ? bs_ : 0.f;
                            bias1 = (ti + 1 > si) ? bs_ : 0.f;
                        } else if (h == 1) {
                            float msv = g_mag1[b * S_ + si];
                            bias0 = (msv * g_mag1[b * S_ + ti]     > meanv) ? bs_ : 0.f;
                            bias1 = (msv * g_mag1[b * S_ + ti + 1] > meanv) ? bs_ : 0.f;
                        } else if (h == 2) {
                            bias0 = g_prox[abs(ti - si)] * bs_;
                            bias1 = g_prox[abs(ti + 1 - si)] * bs_;
                        } else {
                            float vv = g_v3[b * S_ + si];
                            bias0 = (vv * g_v3[b * S_ + ti]     > 0.5f) ? bs_ : 0.f;
                            bias1 = (vv * g_v3[b * S_ + ti + 1] > 0.5f) ? bs_ : 0.f;
                        }
                        v0 = __expf(v0 + bias0);
                        v1 = __expf(v1 + bias1);
                        *(__half2*)(Ch + co) = __floats2half2_rn(v0, v1);
                    } else if (emode == 1) {
                        if (rowScale) {
                            float rs = rowScale[(long long)z * S_ + m];
                            v0 *= rs; v1 *= rs;
                        }
                        *(__half2*)(Ch + co) = __floats2half2_rn(v0, v1);
                    } else {
                        *(float2*)(Cf + co) = make_float2(v0, v1);
                    }
                }
            } else {                                 // Crs==1 (Vt): scalar stores
                #pragma unroll
                for (int q = 0; q < 4; q++) {
                    long long m = mA + (q >> 1) * 8;
                    long long n = nA + (q & 1);
                    float v = alpha * c[q];
                    long long co = Cb + m + n * Ccs;
                    if (emode) Ch[co] = __float2half_rn(v);
                    else       Cf[co] = v;
                }
            }
        }
}

// ---------------- fp32 -> fp16 conversion (8 elems/thread) ----------------
__global__ __launch_bounds__(256) void cvt_kernel(const float* __restrict__ x,
                                                  __half* __restrict__ y) {
    long long i = (long long)blockIdx.x * 256 + threadIdx.x;
    float4 a = ((const float4*)x)[2 * i];
    float4 b = ((const float4*)x)[2 * i + 1];
    __half2 h0 = __floats2half2_rn(a.x, a.y);
    __half2 h1 = __floats2half2_rn(a.z, a.w);
    __half2 h2 = __floats2half2_rn(b.x, b.y);
    __half2 h3 = __floats2half2_rn(b.z, b.w);
    uint4 o;
    o.x = *(u32*)&h0; o.y = *(u32*)&h1; o.z = *(u32*)&h2; o.w = *(u32*)&h3;
    ((uint4*)y)[i] = o;
}

// ---------------- block reductions ----------------
__device__ __forceinline__ float blockReduceSum(float v) {
    __shared__ float sh[33];
    __syncthreads();
    #pragma unroll
    for (int o = 16; o; o >>= 1) v += __shfl_xor_sync(0xffffffffu, v, o);
    if ((threadIdx.x & 31) == 0) sh[threadIdx.x >> 5] = v;
    __syncthreads();
    if (threadIdx.x < 32) {
        v = (threadIdx.x < (blockDim.x >> 5)) ? sh[threadIdx.x] : 0.f;
        #pragma unroll
        for (int o = 16; o; o >>= 1) v += __shfl_xor_sync(0xffffffffu, v, o);
        if (threadIdx.x == 0) sh[32] = v;
    }
    __syncthreads();
    return sh[32];
}

// ---------------- mag1 / v3 / mean / prox ----------------
__global__ __launch_bounds__(256) void mag_kernel(const float* __restrict__ emb) {
    int row = blockIdx.x;
    int tid = threadIdx.x;
    float v = emb[(long long)row * D_ + HD_ + tid];
    float ss = blockReduceSum(v * v);
    if (tid == 0) {
        g_mag1[row] = sqrtf(ss);
        g_v3[row]   = emb[(long long)row * D_ + (D_ - 1)];
    }
}
__global__ __launch_bounds__(256) void mean_kernel() {
    int tid = threadIdx.x;
    float acc = 0.f;
    for (int b = 0; b < B_; b++) {
        float v = 0.f;
        for (int i = tid; i < S_; i += 256) v += g_mag1[b * S_ + i];
        v = blockReduceSum(v);
        acc += v * v;
    }
    if (tid == 0) g_mean = acc / ((float)B_ * (float)S_ * (float)S_);
}
__global__ __launch_bounds__(256) void prox_kernel() {
    int i = blockIdx.x * 256 + threadIdx.x;
    if (i < S_) g_prox[i] = expf(-(float)i / (float)S_);
}

// ---------------- row sums of exp + head-average -> output region 1 ----------------
// One block per (s, b). Reads 4 heads' E rows, writes invR and the fp32 average.
__global__ __launch_bounds__(256) void sumavg_kernel(float* __restrict__ outAvg) {
    int s = blockIdx.x, b = blockIdx.y;
    int tid = threadIdx.x;

    float e[4][8];
    float inv[4];
    #pragma unroll
    for (int h = 0; h < H_; h++) {
        const uint4* row = (const uint4*)(g_W + (((long long)(b * H_ + h)) * S_ + s) * S_);
        uint4 a = row[tid];
        const u32 ar[4] = {a.x, a.y, a.z, a.w};
        float part = 0.f;
        #pragma unroll
        for (int p = 0; p < 4; p++) {
            float2 f = __half22float2(*(const __half2*)&ar[p]);
            e[h][2 * p] = f.x; e[h][2 * p + 1] = f.y;
            part += f.x + f.y;
        }
        float tot = blockReduceSum(part);
        inv[h] = 1.f / tot;
        if (tid == 0) g_invR[(b * H_ + h) * S_ + s] = inv[h];
    }

    float o[8];
    #pragma unroll
    for (int j = 0; j < 8; j++)
        o[j] = 0.25f * (e[0][j] * inv[0] + e[1][j] * inv[1] +
                        e[2][j] * inv[2] + e[3][j] * inv[3]);
    float4* o4 = (float4*)(outAvg + ((long long)b * S_ + s) * S_) + 2 * tid;
    o4[0] = make_float4(o[0], o[1], o[2], o[3]);
    o4[1] = make_float4(o[4], o[5], o[6], o[7]);
}

__global__ void guilt_kernel(float* __restrict__ outG) {
    int i = blockIdx.x * 256 + threadIdx.x;
    if (i < B_ * S_) outG[i] = 1.0f / (float)S_;
}

// ---------------- bias + residual + LayerNorm ----------------
__global__ __launch_bounds__(256) void ln_kernel(const float* __restrict__ emb,
                                                 const float* __restrict__ Wo_b,
                                                 const float* __restrict__ gam,
                                                 const float* __restrict__ bet,
                                                 float* __restrict__ outp) {
    int tok = blockIdx.x;
    int tid = threadIdx.x;
    float y[4];
    float s1 = 0.f;
    #pragma unroll
    for (int i = 0; i < 4; i++) {
        int d = tid + i * 256;
        y[i] = g_wo[(long long)tok * D_ + d] + Wo_b[d] + emb[(long long)tok * D_ + d];
        s1 += y[i];
    }
    s1 = blockReduceSum(s1);
    float mu = s1 * (1.f / (float)D_);
    float s2 = 0.f;
    #pragma unroll
    for (int i = 0; i < 4; i++) { float dd = y[i] - mu; s2 += dd * dd; }
    s2 = blockReduceSum(s2);
    float inv = rsqrtf(s2 * (1.f / (float)D_) + LN_EPS);
    #pragma unroll
    for (int i = 0; i < 4; i++) {
        int d = tid + i * 256;
        outp[(long long)tok * D_ + d] = (y[i] - mu) * inv * gam[d] + bet[d];
    }
}

// ---------------- launch ----------------
extern "C" void kernel_launch(void* const* d_in, const int* in_sizes, int n_in,
                              void* d_out, int out_size) {
    const float* emb   = (const float*)d_in[0];
    const float* Wq    = (const float*)d_in[1];
    const float* Wk    = (const float*)d_in[2];
    const float* Wv    = (const float*)d_in[3];
    const float* bsc   = (const float*)d_in[4];
    const float* Wo_w  = (const float*)d_in[5];
    const float* Wo_b  = (const float*)d_in[6];
    const float* ln_g  = (const float*)d_in[7];
    const float* ln_b  = (const float*)d_in[8];
    float* out = (float*)d_out;

    float *pWoO, *pInvR;
    __half *pW, *pQ, *pK, *pVt, *pE, *pWq, *pWk, *pWv, *pWo, *pC;
    cudaGetSymbolAddress((void**)&pW,   g_W);
    cudaGetSymbolAddress((void**)&pQ,   g_Q);
    cudaGetSymbolAddress((void**)&pK,   g_K);
    cudaGetSymbolAddress((void**)&pVt,  g_Vt);
    cudaGetSymbolAddress((void**)&pE,   g_E);
    cudaGetSymbolAddress((void**)&pWq,  g_Wq);
    cudaGetSymbolAddress((void**)&pWk,  g_Wk);
    cudaGetSymbolAddress((void**)&pWv,  g_Wv);
    cudaGetSymbolAddress((void**)&pWo,  g_Wo);
    cudaGetSymbolAddress((void**)&pC,   g_C);
    cudaGetSymbolAddress((void**)&pWoO, g_wo);
    cudaGetSymbolAddress((void**)&pInvR, g_invR);

    const long long SD  = (long long)S_ * D_;
    const long long SH  = (long long)S_ * HD_;
    const long long SS  = (long long)S_ * S_;
    const long long EP  = (long long)B_ * SD;
    const long long WQP = (long long)H_ * HD_ * HD_;
    const long long WOP = (long long)D_ * D_;

    const int DSMEM_N = 3 * 32768;   // narrow: 96KB, 2 CTAs/SM
    const int DSMEM_W = 3 * 49152;   // wide:  144KB, 1 CTA/SM
    cudaFuncSetAttribute(mma_gemm<128>, cudaFuncAttributeMaxDynamicSharedMemorySize, DSMEM_N);
    cudaFuncSetAttribute(mma_gemm<256>, cudaFuncAttributeMaxDynamicSharedMemorySize, DSMEM_W);

    dim3 blk(256);

    // fp32 -> fp16 conversions
    cvt_kernel<<<(unsigned)(EP / 8 / 256), blk>>>(emb, pE);
    cvt_kernel<<<(unsigned)(WQP / 8 / 256), blk>>>(Wq, pWq);
    cvt_kernel<<<(unsigned)(WQP / 8 / 256), blk>>>(Wk, pWk);
    cvt_kernel<<<(unsigned)(WQP / 8 / 256), blk>>>(Wv, pWv);
    cvt_kernel<<<(unsigned)(WOP / 8 / 256), blk>>>(Wo_w, pWo);

    // Q = X @ Wq^T -> fp16 [b,h,s,e]
    mma_gemm<128><<<dim3(2, 16, 16), blk, DSMEM_N>>>(pE, D_, SD, HD_,
        pWq, HD_, 0, (long long)HD_ * HD_,
        nullptr, pQ, (long long)H_ * SH, SH, HD_, 1, HD_, 1.0f, H_, 1, nullptr, nullptr);
    // K
    mma_gemm<128><<<dim3(2, 16, 16), blk, DSMEM_N>>>(pE, D_, SD, HD_,
        pWk, HD_, 0, (long long)HD_ * HD_,
        nullptr, pK, (long long)H_ * SH, SH, HD_, 1, HD_, 1.0f, H_, 1, nullptr, nullptr);
    // V, stored transposed [b,h,e,t]
    mma_gemm<128><<<dim3(2, 16, 16), blk, DSMEM_N>>>(pE, D_, SD, HD_,
        pWv, HD_, 0, (long long)HD_ * HD_,
        nullptr, pVt, (long long)H_ * HD_ * S_, (long long)HD_ * S_, 1, S_, HD_, 1.0f, H_, 1,
        nullptr, nullptr);

    // mag1 / v3 / intent mean / prox table  (consumed by the scores epilogue)
    mag_kernel<<<B_ * S_, blk>>>(emb);
    mean_kernel<<<1, blk>>>();
    prox_kernel<<<S_ / 256, blk>>>();

    // E = exp(Q@K^T / 16 + bias) -> fp16 g_W  (fused bias+exp epilogue)
    mma_gemm<128><<<dim3(16, 16, 16), blk, DSMEM_N>>>(pQ, HD_, (long long)H_ * SH, SH,
        pK, HD_, (long long)H_ * SH, SH,
        nullptr, pW, (long long)H_ * SS, SS, S_, 1, HD_, 0.0625f, H_, 2, bsc, nullptr);

    // row sums -> invR; head-average -> output region 1
    sumavg_kernel<<<dim3(S_, B_), blk>>>(out + EP);
    guilt_kernel<<<(B_ * S_ + 255) / 256, blk>>>(out + EP + (long long)B_ * SS);

    // attended = (E @ V) * invR -> concat fp16  (wide: E read exactly once)
    mma_gemm<256><<<dim3(1, 16, 16), blk, DSMEM_W>>>(pW, S_, (long long)H_ * SS, SS,
        pVt, S_, (long long)H_ * HD_ * S_, (long long)HD_ * S_,
        nullptr, pC, SD, HD_, D_, 1, S_, 1.0f, H_, 1, nullptr, pInvR);

    // out_pre = concat @ Wo^T -> fp32 g_wo
    mma_gemm<128><<<dim3(8, 64, 1), blk, DSMEM_N>>>(pC, D_, 0, 0,
        pWo, D_, 0, 0,
        pWoO, nullptr, 0, 0, D_, 1, D_, 1.0f, 1, 0, nullptr, nullptr);

    // + Wo_b + residual + LayerNorm -> output region 0
    ln_kernel<<<B_ * S_, blk>>>(emb, Wo_b, ln_g, ln_b, out);
}